// round 15
// baseline (speedup 1.0000x reference)
#include <cuda_runtime.h>
#include <cuda_fp16.h>
#include <math.h>
#include <stdint.h>

#define Nn 6000
#define Ee 120000
#define Dd 128
#define Hh 4
#define Cc 384

// ---------------- scratch (device globals) ----------------
__device__ __align__(16) float g_nodes[Nn * Dd];
__device__ __align__(16) float g_eattr[Ee * Dd];
__device__ __align__(16) float g_nupd[Ee * Dd];
__device__ __align__(16) float g_scores[Ee * Hh];
__device__ __align__(16) float g_upd[Nn * Dd];
__device__ __align__(16) __half g_nodesH[Nn * Dd], g_nodesL[Nn * Dd];
__device__ __align__(16) __half g_eatH[Ee * Dd], g_eatL[Ee * Dd];
__device__ __align__(16) __half g_b1H[Ee * Dd], g_b1L[Ee * Dd];
__device__ __align__(16) __half g_b2H[Ee * Dd], g_b2L[Ee * Dd];
__device__ __align__(16) __half g_aggH[Nn * 4 * Dd], g_aggL[Nn * 4 * Dd];
__device__ int g_cnt[Nn];
__device__ int g_off[Nn + 1];
__device__ int g_cur[Nn];
__device__ int g_csr[Ee];
#define WT_LAYER 557056
__device__ __align__(16) __half g_wT[2 * WT_LAYER];

__device__ __forceinline__ float gelu_f(float x) {
    return 0.5f * x * (1.0f + erff(x * 0.70710678118654752f));
}
__device__ __forceinline__ uint32_t smem_u32(const void* p) {
    uint32_t a;
    asm("{ .reg .u64 t; cvta.to.shared.u64 t, %1; cvt.u32.u64 %0, t; }" : "=r"(a) : "l"(p));
    return a;
}
__device__ __forceinline__ void ldsm4(uint32_t* r, uint32_t addr) {
    asm volatile("ldmatrix.sync.aligned.m8n8.x4.shared.b16 {%0,%1,%2,%3}, [%4];"
                 : "=r"(r[0]), "=r"(r[1]), "=r"(r[2]), "=r"(r[3]) : "r"(addr));
}
__device__ __forceinline__ void mma16816(float* d, const uint32_t* a, const uint32_t* b) {
    asm volatile("mma.sync.aligned.m16n8k16.row.col.f32.f16.f16.f32 "
                 "{%0,%1,%2,%3}, {%4,%5,%6,%7}, {%8,%9}, {%0,%1,%2,%3};"
                 : "+f"(d[0]), "+f"(d[1]), "+f"(d[2]), "+f"(d[3])
                 : "r"(a[0]), "r"(a[1]), "r"(a[2]), "r"(a[3]), "r"(b[0]), "r"(b[1]));
}
__device__ __forceinline__ void split2h(float x, __half& h, __half& l) {
    h = __float2half_rn(x);
    l = __float2half_rn(x - __half2float(h));
}
__device__ __forceinline__ uint32_t packh(__half a, __half b) {
    return ((uint32_t)__half_as_ushort(b) << 16) | __half_as_ushort(a);
}
__device__ __forceinline__ void cp16(uint32_t saddr, const void* g) {
    asm volatile("cp.async.ca.shared.global [%0], [%1], 16;" :: "r"(saddr), "l"(g));
}
#define CP_COMMIT() asm volatile("cp.async.commit_group;" ::: "memory")
#define CP_WAIT1()  asm volatile("cp.async.wait_group 1;" ::: "memory")
#define CP_WAIT0()  asm volatile("cp.async.wait_group 0;" ::: "memory")

// ---------------- HMMA GEMM, fp16 2-pass, 3-stage pipeline, fused epilogues ----------------
// act: 0 none, 1 gelu, 2 score, 3 LayerNorm(pre + resid) with gamma/beta (N must be 128)
#define PITCH 80
#define ARR 10240
#define BUFSTR 30720
#define SM_PART 92160
#define SM_TOTAL 94208

__global__ void __launch_bounds__(256) gemm_tc(
    int M, int K,
    const __half* __restrict__ AhG, const __half* __restrict__ AlG,
    const __half* __restrict__ BT,
    const float* __restrict__ bias,
    float* __restrict__ Cout,
    __half* __restrict__ CoH, __half* __restrict__ CoL, int ldc,
    int act, int featMode, int outSplit,
    const __half* __restrict__ ndH, const __half* __restrict__ ndL,
    const __half* __restrict__ eaH, const __half* __restrict__ eaL,
    const int* __restrict__ srcI, const int* __restrict__ snkI,
    const float* __restrict__ aAv, const float* __restrict__ aAb,
    const float* __restrict__ resid, const float* __restrict__ lnG,
    const float* __restrict__ lnB, float* __restrict__ rawOut)
{
    extern __shared__ char sm[];
    const uint32_t sb = smem_u32(sm);
    const int tid = threadIdx.x, wid = tid >> 5, lane = tid & 31;
    const int m0 = blockIdx.y * 128, n0 = blockIdx.x * 128, z = blockIdx.z;
    if (act == 2) {
        size_t zo = (size_t)z * K * 128;
        BT += zo; bias += z * 128; aAv += z * 128;
    }
    const int mrow0 = (wid & 3) * 32;
    const int ncol0 = (wid >> 2) * 64;
    const int rowoff = ((lane >> 3) & 1) * 8 + (lane & 7);
    const int coloff = (lane >> 4) * 8;

    const int lr0 = tid >> 2, lg0 = (tid & 3) << 3;
    const int lr1 = (tid + 256) >> 2, lg1 = ((tid + 256) & 3) << 3;

    int mm0 = m0 + lr0; if (mm0 >= M) mm0 = M - 1;
    int mm1 = m0 + lr1; if (mm1 >= M) mm1 = M - 1;
    int s0 = 0, t0 = 0, s1 = 0, t1 = 0;
    if (featMode) {
        s0 = srcI[mm0]; t0 = snkI[mm0];
        s1 = srcI[mm1]; t1 = snkI[mm1];
    }

    auto issue_chunk = [&](int c) {
        const uint32_t bb = sb + (uint32_t)(c % 3) * BUFSTR;
        const int k0 = c << 5;
#pragma unroll
        for (int it = 0; it < 2; ++it) {
            int r = it ? lr1 : lr0, g = it ? lg1 : lg0;
            int mm = it ? mm1 : mm0;
            int kg = k0 + g;
            const __half *ph, *pl;
            if (!featMode) { ph = AhG + (size_t)mm * K + kg; pl = AlG + (size_t)mm * K + kg; }
            else if (kg < 128) { int s = it ? s1 : s0; ph = ndH + (size_t)s * 128 + kg; pl = ndL + (size_t)s * 128 + kg; }
            else if (kg < 256) { int s = it ? t1 : t0; ph = ndH + (size_t)s * 128 + (kg - 128); pl = ndL + (size_t)s * 128 + (kg - 128); }
            else { ph = eaH + (size_t)mm * 128 + (kg - 256); pl = eaL + (size_t)mm * 128 + (kg - 256); }
            uint32_t off = (uint32_t)(r * PITCH + g * 2);
            cp16(bb + off, ph);
            cp16(bb + ARR + off, pl);
        }
#pragma unroll
        for (int it = 0; it < 2; ++it) {
            int r = it ? lr1 : lr0, g = it ? lg1 : lg0;
            size_t so = (size_t)(n0 + r) * K + k0 + g;
            uint32_t off = (uint32_t)(r * PITCH + g * 2);
            cp16(bb + 2 * ARR + off, BT + so);
        }
        CP_COMMIT();
    };

    float acc[2][8][4];
#pragma unroll
    for (int i = 0; i < 2; i++)
#pragma unroll
        for (int j = 0; j < 8; j++)
#pragma unroll
            for (int q = 0; q < 4; q++) acc[i][j][q] = 0.f;

    const int nCh = K >> 5;
    issue_chunk(0);
    if (nCh > 1) issue_chunk(1);
    for (int c = 0; c < nCh; ++c) {
        if (c + 1 < nCh) CP_WAIT1();
        else CP_WAIT0();
        __syncthreads();
        const uint32_t bb = sb + (uint32_t)(c % 3) * BUFSTR;
#pragma unroll
        for (int ks = 0; ks < 2; ++ks) {
            const uint32_t kb = (uint32_t)((ks * 16 + coloff) * 2);
            uint32_t ah[2][4], al[2][4];
#pragma unroll
            for (int ma = 0; ma < 2; ++ma) {
                uint32_t ro = (uint32_t)((mrow0 + ma * 16 + rowoff) * PITCH) + kb;
                ldsm4(ah[ma], bb + ro);
                ldsm4(al[ma], bb + ARR + ro);
            }
            uint32_t bh[8][2];
#pragma unroll
            for (int ng = 0; ng < 4; ++ng) {
                uint32_t ro = (uint32_t)((ncol0 + ng * 16 + rowoff) * PITCH) + kb;
                uint32_t t[4];
                ldsm4(t, bb + 2 * ARR + ro);
                bh[2 * ng][0] = t[0]; bh[2 * ng][1] = t[2];
                bh[2 * ng + 1][0] = t[1]; bh[2 * ng + 1][1] = t[3];
            }
#pragma unroll
            for (int ma = 0; ma < 2; ++ma)
#pragma unroll
                for (int na = 0; na < 8; ++na) mma16816(acc[ma][na], ah[ma], bh[na]);
#pragma unroll
            for (int ma = 0; ma < 2; ++ma)
#pragma unroll
                for (int na = 0; na < 8; ++na) mma16816(acc[ma][na], al[ma], bh[na]);
        }
        if (c + 2 < nCh) issue_chunk(c + 2);
    }

    // ---- epilogue ----
    const int qr = lane >> 2, qc = (lane & 3) * 2;
    if (act == 2) {
        float (*part)[2] = (float(*)[2])(sm + SM_PART);
        const int nh = wid >> 2;
        float s[2][2] = {{0.f, 0.f}, {0.f, 0.f}};
#pragma unroll
        for (int ma = 0; ma < 2; ++ma)
#pragma unroll
            for (int na = 0; na < 8; ++na) {
                int n = ncol0 + na * 8 + qc;
#pragma unroll
                for (int j = 0; j < 2; ++j) {
                    float v0 = acc[ma][na][j] + bias[n + j];
                    v0 = v0 > 0.f ? v0 : 0.2f * v0;
                    s[ma][0] += v0 * aAv[n + j];
                    float v1 = acc[ma][na][2 + j] + bias[n + j];
                    v1 = v1 > 0.f ? v1 : 0.2f * v1;
                    s[ma][1] += v1 * aAv[n + j];
                }
            }
#pragma unroll
        for (int ma = 0; ma < 2; ++ma)
#pragma unroll
            for (int g = 0; g < 2; ++g) {
                s[ma][g] += __shfl_xor_sync(0xffffffffu, s[ma][g], 1);
                s[ma][g] += __shfl_xor_sync(0xffffffffu, s[ma][g], 2);
            }
        __syncthreads();
        if ((lane & 3) == 0) {
#pragma unroll
            for (int ma = 0; ma < 2; ++ma) {
                part[mrow0 + ma * 16 + qr][nh] = s[ma][0];
                part[mrow0 + ma * 16 + 8 + qr][nh] = s[ma][1];
            }
        }
        __syncthreads();
        if (tid < 128) {
            int m = m0 + tid;
            if (m < M) Cout[(size_t)m * 4 + z] = part[tid][0] + part[tid][1] + aAb[z];
        }
        return;
    }
    if (act == 3) {
        // fused LayerNorm: pre = acc+bias (opt rawOut), o = pre + resid,
        // out = (o - mean)/std * lnG + lnB   (full 128-col rows)
        float (*pS)[2] = (float(*)[2])(sm + SM_PART);
        float (*pQ)[2] = (float(*)[2])(sm + SM_PART + 1024);
        const int nh = wid >> 2;
        float s[2][2] = {{0.f, 0.f}, {0.f, 0.f}};
        float q[2][2] = {{0.f, 0.f}, {0.f, 0.f}};
#pragma unroll
        for (int ma = 0; ma < 2; ++ma) {
            int mA = m0 + mrow0 + ma * 16 + qr;
            int mB = mA + 8;
#pragma unroll
            for (int na = 0; na < 8; ++na) {
                int n = ncol0 + na * 8 + qc;
                float pA0 = acc[ma][na][0] + bias[n];
                float pA1 = acc[ma][na][1] + bias[n + 1];
                float pB0 = acc[ma][na][2] + bias[n];
                float pB1 = acc[ma][na][3] + bias[n + 1];
                float oA0 = 0.f, oA1 = 0.f, oB0 = 0.f, oB1 = 0.f;
                if (mA < M) {
                    if (rawOut) *(float2*)(rawOut + (size_t)mA * 128 + n) = make_float2(pA0, pA1);
                    oA0 = pA0 + resid[(size_t)mA * 128 + n];
                    oA1 = pA1 + resid[(size_t)mA * 128 + n + 1];
                }
                if (mB < M) {
                    if (rawOut) *(float2*)(rawOut + (size_t)mB * 128 + n) = make_float2(pB0, pB1);
                    oB0 = pB0 + resid[(size_t)mB * 128 + n];
                    oB1 = pB1 + resid[(size_t)mB * 128 + n + 1];
                }
                acc[ma][na][0] = oA0; acc[ma][na][1] = oA1;
                acc[ma][na][2] = oB0; acc[ma][na][3] = oB1;
                s[ma][0] += oA0 + oA1; q[ma][0] += oA0 * oA0 + oA1 * oA1;
                s[ma][1] += oB0 + oB1; q[ma][1] += oB0 * oB0 + oB1 * oB1;
            }
        }
#pragma unroll
        for (int ma = 0; ma < 2; ++ma)
#pragma unroll
            for (int g2 = 0; g2 < 2; ++g2) {
                s[ma][g2] += __shfl_xor_sync(0xffffffffu, s[ma][g2], 1);
                s[ma][g2] += __shfl_xor_sync(0xffffffffu, s[ma][g2], 2);
                q[ma][g2] += __shfl_xor_sync(0xffffffffu, q[ma][g2], 1);
                q[ma][g2] += __shfl_xor_sync(0xffffffffu, q[ma][g2], 2);
            }
        __syncthreads();
        if ((lane & 3) == 0) {
#pragma unroll
            for (int ma = 0; ma < 2; ++ma) {
                int r = mrow0 + ma * 16 + qr;
                pS[r][nh] = s[ma][0]; pQ[r][nh] = q[ma][0];
                pS[r + 8][nh] = s[ma][1]; pQ[r + 8][nh] = q[ma][1];
            }
        }
        __syncthreads();
        float mean_[2][2], rstd_[2][2];
#pragma unroll
        for (int ma = 0; ma < 2; ++ma)
#pragma unroll
            for (int g2 = 0; g2 < 2; ++g2) {
                int r = mrow0 + ma * 16 + g2 * 8 + qr;
                float mu = (pS[r][0] + pS[r][1]) * (1.0f / 128.0f);
                float var = (pQ[r][0] + pQ[r][1]) * (1.0f / 128.0f) - mu * mu;
                mean_[ma][g2] = mu;
                rstd_[ma][g2] = rsqrtf(var + 1e-5f);
            }
#pragma unroll
        for (int ma = 0; ma < 2; ++ma) {
            int mA = m0 + mrow0 + ma * 16 + qr;
            int mB = mA + 8;
#pragma unroll
            for (int na = 0; na < 8; ++na) {
                int n = ncol0 + na * 8 + qc;
                float g0 = lnG[n], g1 = lnG[n + 1], b0 = lnB[n], b1 = lnB[n + 1];
                if (mA < M) {
                    float yA0 = (acc[ma][na][0] - mean_[ma][0]) * rstd_[ma][0] * g0 + b0;
                    float yA1 = (acc[ma][na][1] - mean_[ma][0]) * rstd_[ma][0] * g1 + b1;
                    *(float2*)(Cout + (size_t)mA * 128 + n) = make_float2(yA0, yA1);
                    if (outSplit) {
                        __half h0, l0, h1, l1;
                        split2h(yA0, h0, l0); split2h(yA1, h1, l1);
                        *(uint32_t*)(CoH + (size_t)mA * 128 + n) = packh(h0, h1);
                        *(uint32_t*)(CoL + (size_t)mA * 128 + n) = packh(l0, l1);
                    }
                }
                if (mB < M) {
                    float yB0 = (acc[ma][na][2] - mean_[ma][1]) * rstd_[ma][1] * g0 + b0;
                    float yB1 = (acc[ma][na][3] - mean_[ma][1]) * rstd_[ma][1] * g1 + b1;
                    *(float2*)(Cout + (size_t)mB * 128 + n) = make_float2(yB0, yB1);
                    if (outSplit) {
                        __half h0, l0, h1, l1;
                        split2h(yB0, h0, l0); split2h(yB1, h1, l1);
                        *(uint32_t*)(CoH + (size_t)mB * 128 + n) = packh(h0, h1);
                        *(uint32_t*)(CoL + (size_t)mB * 128 + n) = packh(l0, l1);
                    }
                }
            }
        }
        return;
    }
#pragma unroll
    for (int ma = 0; ma < 2; ++ma) {
        int mA = m0 + mrow0 + ma * 16 + qr;
        int mB = mA + 8;
#pragma unroll
        for (int na = 0; na < 8; ++na) {
            int n = n0 + ncol0 + na * 8 + qc;
            float2 oA, oB;
            oA.x = acc[ma][na][0] + bias[n];
            oA.y = acc[ma][na][1] + bias[n + 1];
            oB.x = acc[ma][na][2] + bias[n];
            oB.y = acc[ma][na][3] + bias[n + 1];
            if (act == 1) {
                oA.x = gelu_f(oA.x); oA.y = gelu_f(oA.y);
                oB.x = gelu_f(oB.x); oB.y = gelu_f(oB.y);
            }
            if (outSplit) {
                __half h0, l0, h1, l1;
                if (mA < M) {
                    split2h(oA.x, h0, l0); split2h(oA.y, h1, l1);
                    *(uint32_t*)(CoH + (size_t)mA * ldc + n) = packh(h0, h1);
                    *(uint32_t*)(CoL + (size_t)mA * ldc + n) = packh(l0, l1);
                }
                if (mB < M) {
                    split2h(oB.x, h0, l0); split2h(oB.y, h1, l1);
                    *(uint32_t*)(CoH + (size_t)mB * ldc + n) = packh(h0, h1);
                    *(uint32_t*)(CoL + (size_t)mB * ldc + n) = packh(l0, l1);
                }
            } else {
                if (mA < M) *(float2*)(Cout + (size_t)mA * ldc + n) = oA;
                if (mB < M) *(float2*)(Cout + (size_t)mB * ldc + n) = oB;
            }
        }
    }
}

// ---------------- weight transpose to fp16 ----------------
struct TEnt { const float* src; int dstOff; int K; int N; };
struct TTab { TEnt e[26]; };
__global__ void tsplit_k(TTab tab) {
    TEnt E = tab.e[blockIdx.y];
    int i = blockIdx.x * 256 + threadIdx.x;
    int total = E.K * E.N;
    if (i >= total) return;
    int k = i / E.N, n = i % E.N;
    g_wT[E.dstOff + (size_t)n * E.K + k] = __float2half_rn(E.src[i]);
}

// ---------------- setup ----------------
__global__ void embed_k(const int* __restrict__ seq, const float* __restrict__ emb) {
    int i = blockIdx.x * 256 + threadIdx.x;
    if (i < Nn * 128) {
        int nidx = i >> 7, d = i & 127;
        float x = emb[seq[nidx] * 128 + d];
        g_nodes[i] = x;
        __half h, l;
        split2h(x, h, l);
        g_nodesH[i] = h; g_nodesL[i] = l;
    }
}
__global__ void rbf_k(const float* __restrict__ dist, const float* __restrict__ W,
                      const float* __restrict__ b) {
    __shared__ float r[16];
    int e = blockIdx.x;
    int t = threadIdx.x;
    if (t < 16) {
        float mu = 2.0f + (20.0f / 15.0f) * (float)t;
        float x = (dist[e] - mu) * (1.0f / 1.25f);
        r[t] = expf(-x * x) + 1e-8f;
    }
    __syncthreads();
    float s = b[t];
#pragma unroll
    for (int j = 0; j < 16; j++) s += r[j] * W[j * 128 + t];
    long long i = (long long)e * 128 + t;
    g_eattr[i] = s;
    __half h, l;
    split2h(s, h, l);
    g_eatH[i] = h; g_eatL[i] = l;
}

// ---------------- CSR ----------------
__global__ void zero_cnt_k() {
    int i = blockIdx.x * 256 + threadIdx.x;
    if (i < Nn) g_cnt[i] = 0;
}
__global__ void count_k(const int* __restrict__ snk) {
    int e = blockIdx.x * 256 + threadIdx.x;
    if (e < Ee) atomicAdd(&g_cnt[snk[e]], 1);
}
__global__ void __launch_bounds__(1024) scan_k() {
    __shared__ int s[1024];
    int t = threadIdx.x;
    const int CH = (Nn + 1023) / 1024;
    int st = t * CH;
    int en = st + CH; if (en > Nn) en = Nn; if (st > Nn) st = Nn;
    int loc = 0;
    for (int i = st; i < en; i++) loc += g_cnt[i];
    s[t] = loc;
    __syncthreads();
    for (int d = 1; d < 1024; d <<= 1) {
        int v = (t >= d) ? s[t - d] : 0;
        __syncthreads();
        s[t] += v;
        __syncthreads();
    }
    int run = (t == 0) ? 0 : s[t - 1];
    for (int i = st; i < en; i++) {
        g_off[i] = run; g_cur[i] = run; run += g_cnt[i];
    }
    if (t == 1023) g_off[Nn] = s[1023];
}
__global__ void place_k(const int* __restrict__ snk) {
    int e = blockIdx.x * 256 + threadIdx.x;
    if (e < Ee) {
        int p = atomicAdd(&g_cur[snk[e]], 1);
        g_csr[p] = e;
    }
}

// ---------------- per-node softmax + aggregation ----------------
__global__ void __launch_bounds__(128) agg_k() {
    __shared__ float red[4][128];
    int n = blockIdx.x, t = threadIdx.x;
    int beg = g_off[n], end = g_off[n + 1];
    const float4* sc4 = (const float4*)g_scores;

    float mx[4] = {-1e30f, -1e30f, -1e30f, -1e30f};
    for (int i = beg + t; i < end; i += 128) {
        float4 s = sc4[g_csr[i]];
        mx[0] = fmaxf(mx[0], s.x); mx[1] = fmaxf(mx[1], s.y);
        mx[2] = fmaxf(mx[2], s.z); mx[3] = fmaxf(mx[3], s.w);
    }
#pragma unroll
    for (int h = 0; h < 4; h++) red[h][t] = mx[h];
    __syncthreads();
    for (int s = 64; s > 0; s >>= 1) {
        if (t < s)
#pragma unroll
            for (int h = 0; h < 4; h++) red[h][t] = fmaxf(red[h][t], red[h][t + s]);
        __syncthreads();
    }
    float mxf[4];
#pragma unroll
    for (int h = 0; h < 4; h++) mxf[h] = red[h][0];
    __syncthreads();

    float sm[4] = {0.f, 0.f, 0.f, 0.f};
    for (int i = beg + t; i < end; i += 128) {
        float4 s = sc4[g_csr[i]];
        sm[0] += expf(s.x - mxf[0]) + 1e-12f;
        sm[1] += expf(s.y - mxf[1]) + 1e-12f;
        sm[2] += expf(s.z - mxf[2]) + 1e-12f;
        sm[3] += expf(s.w - mxf[3]) + 1e-12f;
    }
#pragma unroll
    for (int h = 0; h < 4; h++) red[h][t] = sm[h];
    __syncthreads();
    for (int s = 64; s > 0; s >>= 1) {
        if (t < s)
#pragma unroll
            for (int h = 0; h < 4; h++) red[h][t] += red[h][t + s];
        __syncthreads();
    }
    float nrm[4];
#pragma unroll
    for (int h = 0; h < 4; h++) nrm[h] = red[h][0];

    float acc[4] = {0.f, 0.f, 0.f, 0.f};
    for (int i = beg; i < end; i++) {
        int e = g_csr[i];
        float4 s = sc4[e];
        float a0 = expf(s.x - mxf[0]) / nrm[0];
        float a1 = expf(s.y - mxf[1]) / nrm[1];
        float a2 = expf(s.z - mxf[2]) / nrm[2];
        float a3 = expf(s.w - mxf[3]) / nrm[3];
        float v = g_nupd[(long long)e * 128 + t];
        acc[0] += a0 * v; acc[1] += a1 * v; acc[2] += a2 * v; acc[3] += a3 * v;
    }
    long long base = (long long)n * 512;
#pragma unroll
    for (int h = 0; h < 4; h++) {
        __half hh, ll;
        split2h(acc[h], hh, ll);
        g_aggH[base + h * 128 + t] = hh;
        g_aggL[base + h * 128 + t] = ll;
    }
}

// ---------------- host ----------------
extern "C" void kernel_launch(void* const* d_in, const int* in_sizes, int n_in,
                              void* d_out, int out_size) {
    const int* seq = (const int*)d_in[0];
    const int* eidx = (const int*)d_in[1];
    const int* srcI = eidx;
    const int* snkI = eidx + Ee;
    const float* dist = (const float*)d_in[2];
    const float* seq_embed = (const float*)d_in[3];
    const float* edge_lin_W = (const float*)d_in[4];
    const float* edge_lin_b = (const float*)d_in[5];
    const float* aW_W = (const float*)d_in[6];
    const float* aW_b = (const float*)d_in[7];
    const float* aA_W = (const float*)d_in[8];
    const float* aA_b = (const float*)d_in[9];
    const float* nmlp_W1 = (const float*)d_in[10];
    const float* nmlp_b1 = (const float*)d_in[11];
    const float* nmlp_W2 = (const float*)d_in[12];
    const float* nmlp_b2 = (const float*)d_in[13];
    const float* nmlp_W3 = (const float*)d_in[14];
    const float* nmlp_b3 = (const float*)d_in[15];
    const float* dmlp_W1 = (const float*)d_in[16];
    const float* dmlp_b1 = (const float*)d_in[17];
    const float* dmlp_W2 = (const float*)d_in[18];
    const float* dmlp_b2 = (const float*)d_in[19];
    const float* emlp_W1 = (const float*)d_in[20];
    const float* emlp_b1 = (const float*)d_in[21];
    const float* emlp_W2 = (const float*)d_in[22];
    const float* emlp_b2 = (const float*)d_in[23];
    const float* emlp_W3 = (const float*)d_in[24];
    const float* emlp_b3 = (const float*)d_in[25];
    const float* aggr_W = (const float*)d_in[26];
    const float* aggr_b = (const float*)d_in[27];
    const float* n1_g = (const float*)d_in[28];
    const float* n1_b = (const float*)d_in[29];
    const float* e_g = (const float*)d_in[30];
    const float* e_b = (const float*)d_in[31];

    float *p_nodes, *p_eattr, *p_nupd, *p_scores, *p_upd;
    __half *pW, *pNh, *pNl, *pEh, *pEl, *pB1h, *pB1l, *pB2h, *pB2l, *pAgh, *pAgl;
    cudaGetSymbolAddress((void**)&p_nodes, g_nodes);
    cudaGetSymbolAddress((void**)&p_eattr, g_eattr);
    cudaGetSymbolAddress((void**)&p_nupd, g_nupd);
    cudaGetSymbolAddress((void**)&p_scores, g_scores);
    cudaGetSymbolAddress((void**)&p_upd, g_upd);
    cudaGetSymbolAddress((void**)&pW, g_wT);
    cudaGetSymbolAddress((void**)&pNh, g_nodesH);
    cudaGetSymbolAddress((void**)&pNl, g_nodesL);
    cudaGetSymbolAddress((void**)&pEh, g_eatH);
    cudaGetSymbolAddress((void**)&pEl, g_eatL);
    cudaGetSymbolAddress((void**)&pB1h, g_b1H);
    cudaGetSymbolAddress((void**)&pB1l, g_b1L);
    cudaGetSymbolAddress((void**)&pB2h, g_b2H);
    cudaGetSymbolAddress((void**)&pB2l, g_b2L);
    cudaGetSymbolAddress((void**)&pAgh, g_aggH);
    cudaGetSymbolAddress((void**)&pAgl, g_aggL);

    cudaFuncSetAttribute(gemm_tc, cudaFuncAttributeMaxDynamicSharedMemorySize, SM_TOTAL);

    TTab tab;
    {
        int idx = 0;
        for (int l = 0; l < 2; l++) {
            int lb = l * WT_LAYER;
            for (int h = 0; h < 4; h++)
                tab.e[idx++] = { aW_W + (size_t)(l * 4 + h) * 384 * 128, lb + h * 49152, 384, 128 };
            tab.e[idx++] = { nmlp_W1 + (size_t)l * 384 * 128, lb + 196608, 384, 128 };
            tab.e[idx++] = { nmlp_W2 + (size_t)l * 128 * 128, lb + 245760, 128, 128 };
            tab.e[idx++] = { nmlp_W3 + (size_t)l * 128 * 128, lb + 262144, 128, 128 };
            tab.e[idx++] = { aggr_W + (size_t)l * 512 * 128, lb + 278528, 512, 128 };
            tab.e[idx++] = { dmlp_W1 + (size_t)l * 128 * 512, lb + 344064, 128, 512 };
            tab.e[idx++] = { dmlp_W2 + (size_t)l * 512 * 128, lb + 409600, 512, 128 };
            tab.e[idx++] = { emlp_W1 + (size_t)l * 384 * 128, lb + 475136, 384, 128 };
            tab.e[idx++] = { emlp_W2 + (size_t)l * 128 * 128, lb + 524288, 128, 128 };
            tab.e[idx++] = { emlp_W3 + (size_t)l * 128 * 128, lb + 540672, 128, 128 };
        }
    }

    auto gemm = [&](int M, int K, int nTile, int zDim,
                    const __half* Ah, const __half* Al, long long wOff,
                    const float* bias, float* Cp, __half* CoH, __half* CoL,
                    int ldc, int act, int feat, int osplit,
                    const float* aAv, const float* aAb,
                    const float* resid, const float* lnG, const float* lnB, float* rawOut) {
        dim3 g(nTile, (M + 127) / 128, zDim);
        gemm_tc<<<g, 256, SM_TOTAL>>>(M, K, Ah, Al, pW + wOff, bias, Cp, CoH, CoL, ldc,
                                      act, feat, osplit, pNh, pNl, pEh, pEl, srcI, snkI,
                                      aAv, aAb, resid, lnG, lnB, rawOut);
    };

    tsplit_k<<<dim3(256, 26), 256>>>(tab);
    embed_k<<<(Nn * 128 + 255) / 256, 256>>>(seq, seq_embed);
    rbf_k<<<Ee, 128>>>(dist, edge_lin_W, edge_lin_b);
    zero_cnt_k<<<(Nn + 255) / 256, 256>>>();
    count_k<<<(Ee + 255) / 256, 256>>>(snkI);
    scan_k<<<1, 1024>>>();
    place_k<<<(Ee + 255) / 256, 256>>>(snkI);

    float* outNodes = (float*)d_out;
    float* outEattr = (float*)d_out + (long long)Nn * 128;

    for (int l = 0; l < 2; l++) {
        long long lb = (long long)l * WT_LAYER;
        // attention scores
        gemm(Ee, Cc, 1, 4, nullptr, nullptr, lb + 0, aW_b + l * 512,
             p_scores, nullptr, nullptr, 0, 2, 1, 0, aA_W + l * 512, aA_b + l * 4,
             nullptr, nullptr, nullptr, nullptr);
        // node-message MLP
        gemm(Ee, Cc, 1, 1, nullptr, nullptr, lb + 196608, nmlp_b1 + l * 128,
             nullptr, pB1h, pB1l, 128, 1, 1, 1, nullptr, nullptr, nullptr, nullptr, nullptr, nullptr);
        gemm(Ee, 128, 1, 1, pB1h, pB1l, lb + 245760, nmlp_b2 + l * 128,
             nullptr, pB2h, pB2l, 128, 1, 0, 1, nullptr, nullptr, nullptr, nullptr, nullptr, nullptr);
        gemm(Ee, 128, 1, 1, pB2h, pB2l, lb + 262144, nmlp_b3 + l * 128,
             p_nupd, nullptr, nullptr, 128, 0, 0, 0, nullptr, nullptr, nullptr, nullptr, nullptr, nullptr);
        agg_k<<<Nn, 128>>>();
        // aggr GEMM + fused LN: upd raw -> p_upd; nodes = LN(nodes + upd) (+ split)
        gemm(Nn, 512, 1, 1, pAgh, pAgl, lb + 278528, aggr_b + l * 128,
             p_nodes, pNh, pNl, 128, 3, 0, 1, nullptr, nullptr,
             p_nodes, n1_g + l * 128, n1_b + l * 128, p_upd);
        // dense MLP; dmlp2 + fused LN: nodes = LN(dense + upd)
        gemm(Nn, 128, 4, 1, pNh, pNl, lb + 344064, dmlp_b1 + l * 512,
             nullptr, pB1h, pB1l, 512, 1, 0, 1, nullptr, nullptr, nullptr, nullptr, nullptr, nullptr);
        gemm(Nn, 512, 1, 1, pB1h, pB1l, lb + 409600, dmlp_b2 + l * 128,
             l == 1 ? outNodes : p_nodes, pNh, pNl, 128, 3, 0, 1, nullptr, nullptr,
             p_upd, n1_g + l * 128, n1_b + l * 128, nullptr);
        // edge MLP; emlp3 + fused LN: eattr = LN(eattr + eu)
        gemm(Ee, Cc, 1, 1, nullptr, nullptr, lb + 475136, emlp_b1 + l * 128,
             nullptr, pB1h, pB1l, 128, 1, 1, 1, nullptr, nullptr, nullptr, nullptr, nullptr, nullptr);
        gemm(Ee, 128, 1, 1, pB1h, pB1l, lb + 524288, emlp_b2 + l * 128,
             nullptr, pB2h, pB2l, 128, 1, 0, 1, nullptr, nullptr, nullptr, nullptr, nullptr, nullptr);
        gemm(Ee, 128, 1, 1, pB2h, pB2l, lb + 540672, emlp_b3 + l * 128,
             l == 1 ? outEattr : p_eattr, pEh, pEl, 128, 3, 0, l == 0 ? 1 : 0, nullptr, nullptr,
             p_eattr, e_g + l * 128, e_b + l * 128, nullptr);
    }
}

// round 16
// speedup vs baseline: 1.1910x; 1.1910x over previous
#include <cuda_runtime.h>
#include <cuda_fp16.h>
#include <math.h>
#include <stdint.h>

#define Nn 6000
#define Ee 120000
#define Dd 128
#define Hh 4
#define Cc 384

// ---------------- scratch (device globals) ----------------
__device__ __align__(16) float g_nodes[Nn * Dd];
__device__ __align__(16) float g_eattr[Ee * Dd];
__device__ __align__(16) float g_nupd[Ee * Dd];
__device__ __align__(16) float g_scores[Ee * Hh];
__device__ __align__(16) float g_upd[Nn * Dd];
__device__ __align__(16) __half g_nodesH[Nn * Dd], g_nodesL[Nn * Dd];
__device__ __align__(16) __half g_eatH[Ee * Dd], g_eatL[Ee * Dd];
__device__ __align__(16) __half g_b1H[Ee * Dd], g_b1L[Ee * Dd];
__device__ __align__(16) __half g_b2H[Ee * Dd], g_b2L[Ee * Dd];
__device__ __align__(16) __half g_aggH[Nn * 4 * Dd], g_aggL[Nn * 4 * Dd];
__device__ int g_cnt[Nn];
__device__ int g_off[Nn + 1];
__device__ int g_cur[Nn];
__device__ int g_csr[Ee];
#define WT_LAYER 557056
__device__ __align__(16) __half g_wT[2 * WT_LAYER];

__device__ __forceinline__ float gelu_f(float x) {
    return 0.5f * x * (1.0f + erff(x * 0.70710678118654752f));
}
__device__ __forceinline__ uint32_t smem_u32(const void* p) {
    uint32_t a;
    asm("{ .reg .u64 t; cvta.to.shared.u64 t, %1; cvt.u32.u64 %0, t; }" : "=r"(a) : "l"(p));
    return a;
}
__device__ __forceinline__ void ldsm4(uint32_t* r, uint32_t addr) {
    asm volatile("ldmatrix.sync.aligned.m8n8.x4.shared.b16 {%0,%1,%2,%3}, [%4];"
                 : "=r"(r[0]), "=r"(r[1]), "=r"(r[2]), "=r"(r[3]) : "r"(addr));
}
__device__ __forceinline__ void mma16816(float* d, const uint32_t* a, const uint32_t* b) {
    asm volatile("mma.sync.aligned.m16n8k16.row.col.f32.f16.f16.f32 "
                 "{%0,%1,%2,%3}, {%4,%5,%6,%7}, {%8,%9}, {%0,%1,%2,%3};"
                 : "+f"(d[0]), "+f"(d[1]), "+f"(d[2]), "+f"(d[3])
                 : "r"(a[0]), "r"(a[1]), "r"(a[2]), "r"(a[3]), "r"(b[0]), "r"(b[1]));
}
__device__ __forceinline__ void split2h(float x, __half& h, __half& l) {
    h = __float2half_rn(x);
    l = __float2half_rn(x - __half2float(h));
}
__device__ __forceinline__ uint32_t packh(__half a, __half b) {
    return ((uint32_t)__half_as_ushort(b) << 16) | __half_as_ushort(a);
}
__device__ __forceinline__ void cp16(uint32_t saddr, const void* g) {
    asm volatile("cp.async.ca.shared.global [%0], [%1], 16;" :: "r"(saddr), "l"(g));
}
#define CP_COMMIT() asm volatile("cp.async.commit_group;" ::: "memory")
#define CP_WAIT1()  asm volatile("cp.async.wait_group 1;" ::: "memory")
#define CP_WAIT0()  asm volatile("cp.async.wait_group 0;" ::: "memory")

#define PITCH 80
#define ARR 10240
#define BUFSTR 30720
#define SM_PART 92160
#define SM_TOTAL 93184
#define SM_TOTAL_LN 94208

// ---------------- R13-best generic GEMM (act: 0 none, 1 gelu, 2 score) ----------------
__global__ void __launch_bounds__(256) gemm_tc(
    int M, int K,
    const __half* __restrict__ AhG, const __half* __restrict__ AlG,
    const __half* __restrict__ BT,
    const float* __restrict__ bias,
    float* __restrict__ Cout,
    __half* __restrict__ CoH, __half* __restrict__ CoL, int ldc,
    int act, int featMode, int outSplit,
    const __half* __restrict__ ndH, const __half* __restrict__ ndL,
    const __half* __restrict__ eaH, const __half* __restrict__ eaL,
    const int* __restrict__ srcI, const int* __restrict__ snkI,
    const float* __restrict__ aAv, const float* __restrict__ aAb)
{
    extern __shared__ char sm[];
    const uint32_t sb = smem_u32(sm);
    const int tid = threadIdx.x, wid = tid >> 5, lane = tid & 31;
    const int m0 = blockIdx.y * 128, n0 = blockIdx.x * 128, z = blockIdx.z;
    if (act == 2) {
        size_t zo = (size_t)z * K * 128;
        BT += zo; bias += z * 128; aAv += z * 128;
    }
    const int mrow0 = (wid & 3) * 32;
    const int ncol0 = (wid >> 2) * 64;
    const int rowoff = ((lane >> 3) & 1) * 8 + (lane & 7);
    const int coloff = (lane >> 4) * 8;

    const int lr0 = tid >> 2, lg0 = (tid & 3) << 3;
    const int lr1 = (tid + 256) >> 2, lg1 = ((tid + 256) & 3) << 3;

    int mm0 = m0 + lr0; if (mm0 >= M) mm0 = M - 1;
    int mm1 = m0 + lr1; if (mm1 >= M) mm1 = M - 1;
    int s0 = 0, t0 = 0, s1 = 0, t1 = 0;
    if (featMode) {
        s0 = srcI[mm0]; t0 = snkI[mm0];
        s1 = srcI[mm1]; t1 = snkI[mm1];
    }

    auto issue_chunk = [&](int c) {
        const uint32_t bb = sb + (uint32_t)(c % 3) * BUFSTR;
        const int k0 = c << 5;
#pragma unroll
        for (int it = 0; it < 2; ++it) {
            int r = it ? lr1 : lr0, g = it ? lg1 : lg0;
            int mm = it ? mm1 : mm0;
            int kg = k0 + g;
            const __half *ph, *pl;
            if (!featMode) { ph = AhG + (size_t)mm * K + kg; pl = AlG + (size_t)mm * K + kg; }
            else if (kg < 128) { int s = it ? s1 : s0; ph = ndH + (size_t)s * 128 + kg; pl = ndL + (size_t)s * 128 + kg; }
            else if (kg < 256) { int s = it ? t1 : t0; ph = ndH + (size_t)s * 128 + (kg - 128); pl = ndL + (size_t)s * 128 + (kg - 128); }
            else { ph = eaH + (size_t)mm * 128 + (kg - 256); pl = eaL + (size_t)mm * 128 + (kg - 256); }
            uint32_t off = (uint32_t)(r * PITCH + g * 2);
            cp16(bb + off, ph);
            cp16(bb + ARR + off, pl);
        }
#pragma unroll
        for (int it = 0; it < 2; ++it) {
            int r = it ? lr1 : lr0, g = it ? lg1 : lg0;
            size_t so = (size_t)(n0 + r) * K + k0 + g;
            uint32_t off = (uint32_t)(r * PITCH + g * 2);
            cp16(bb + 2 * ARR + off, BT + so);
        }
        CP_COMMIT();
    };

    float acc[2][8][4];
#pragma unroll
    for (int i = 0; i < 2; i++)
#pragma unroll
        for (int j = 0; j < 8; j++)
#pragma unroll
            for (int q = 0; q < 4; q++) acc[i][j][q] = 0.f;

    const int nCh = K >> 5;
    issue_chunk(0);
    if (nCh > 1) issue_chunk(1);
    for (int c = 0; c < nCh; ++c) {
        if (c + 1 < nCh) CP_WAIT1();
        else CP_WAIT0();
        __syncthreads();
        const uint32_t bb = sb + (uint32_t)(c % 3) * BUFSTR;
#pragma unroll
        for (int ks = 0; ks < 2; ++ks) {
            const uint32_t kb = (uint32_t)((ks * 16 + coloff) * 2);
            uint32_t ah[2][4], al[2][4];
#pragma unroll
            for (int ma = 0; ma < 2; ++ma) {
                uint32_t ro = (uint32_t)((mrow0 + ma * 16 + rowoff) * PITCH) + kb;
                ldsm4(ah[ma], bb + ro);
                ldsm4(al[ma], bb + ARR + ro);
            }
            uint32_t bh[8][2];
#pragma unroll
            for (int ng = 0; ng < 4; ++ng) {
                uint32_t ro = (uint32_t)((ncol0 + ng * 16 + rowoff) * PITCH) + kb;
                uint32_t t[4];
                ldsm4(t, bb + 2 * ARR + ro);
                bh[2 * ng][0] = t[0]; bh[2 * ng][1] = t[2];
                bh[2 * ng + 1][0] = t[1]; bh[2 * ng + 1][1] = t[3];
            }
#pragma unroll
            for (int ma = 0; ma < 2; ++ma)
#pragma unroll
                for (int na = 0; na < 8; ++na) mma16816(acc[ma][na], ah[ma], bh[na]);
#pragma unroll
            for (int ma = 0; ma < 2; ++ma)
#pragma unroll
                for (int na = 0; na < 8; ++na) mma16816(acc[ma][na], al[ma], bh[na]);
        }
        if (c + 2 < nCh) issue_chunk(c + 2);
    }

    const int qr = lane >> 2, qc = (lane & 3) * 2;
    if (act == 2) {
        float (*part)[2] = (float(*)[2])(sm + SM_PART);
        const int nh = wid >> 2;
        float s[2][2] = {{0.f, 0.f}, {0.f, 0.f}};
#pragma unroll
        for (int ma = 0; ma < 2; ++ma)
#pragma unroll
            for (int na = 0; na < 8; ++na) {
                int n = ncol0 + na * 8 + qc;
#pragma unroll
                for (int j = 0; j < 2; ++j) {
                    float v0 = acc[ma][na][j] + bias[n + j];
                    v0 = v0 > 0.f ? v0 : 0.2f * v0;
                    s[ma][0] += v0 * aAv[n + j];
                    float v1 = acc[ma][na][2 + j] + bias[n + j];
                    v1 = v1 > 0.f ? v1 : 0.2f * v1;
                    s[ma][1] += v1 * aAv[n + j];
                }
            }
#pragma unroll
        for (int ma = 0; ma < 2; ++ma)
#pragma unroll
            for (int g = 0; g < 2; ++g) {
                s[ma][g] += __shfl_xor_sync(0xffffffffu, s[ma][g], 1);
                s[ma][g] += __shfl_xor_sync(0xffffffffu, s[ma][g], 2);
            }
        __syncthreads();
        if ((lane & 3) == 0) {
#pragma unroll
            for (int ma = 0; ma < 2; ++ma) {
                part[mrow0 + ma * 16 + qr][nh] = s[ma][0];
                part[mrow0 + ma * 16 + 8 + qr][nh] = s[ma][1];
            }
        }
        __syncthreads();
        if (tid < 128) {
            int m = m0 + tid;
            if (m < M) Cout[(size_t)m * 4 + z] = part[tid][0] + part[tid][1] + aAb[z];
        }
        return;
    }
#pragma unroll
    for (int ma = 0; ma < 2; ++ma) {
        int mA = m0 + mrow0 + ma * 16 + qr;
        int mB = mA + 8;
#pragma unroll
        for (int na = 0; na < 8; ++na) {
            int n = n0 + ncol0 + na * 8 + qc;
            float2 oA, oB;
            oA.x = acc[ma][na][0] + bias[n];
            oA.y = acc[ma][na][1] + bias[n + 1];
            oB.x = acc[ma][na][2] + bias[n];
            oB.y = acc[ma][na][3] + bias[n + 1];
            if (act == 1) {
                oA.x = gelu_f(oA.x); oA.y = gelu_f(oA.y);
                oB.x = gelu_f(oB.x); oB.y = gelu_f(oB.y);
            }
            if (outSplit) {
                __half h0, l0, h1, l1;
                if (mA < M) {
                    split2h(oA.x, h0, l0); split2h(oA.y, h1, l1);
                    *(uint32_t*)(CoH + (size_t)mA * ldc + n) = packh(h0, h1);
                    *(uint32_t*)(CoL + (size_t)mA * ldc + n) = packh(l0, l1);
                }
                if (mB < M) {
                    split2h(oB.x, h0, l0); split2h(oB.y, h1, l1);
                    *(uint32_t*)(CoH + (size_t)mB * ldc + n) = packh(h0, h1);
                    *(uint32_t*)(CoL + (size_t)mB * ldc + n) = packh(l0, l1);
                }
            } else {
                if (mA < M) *(float2*)(Cout + (size_t)mA * ldc + n) = oA;
                if (mB < M) *(float2*)(Cout + (size_t)mB * ldc + n) = oB;
            }
        }
    }
}

// ---------------- separate GEMM + fused LayerNorm kernel (N == 128, no featMode) ----------------
__global__ void __launch_bounds__(256) gemm_ln(
    int M, int K,
    const __half* __restrict__ AhG, const __half* __restrict__ AlG,
    const __half* __restrict__ BT,
    const float* __restrict__ bias,
    float* __restrict__ Cout,
    __half* __restrict__ CoH, __half* __restrict__ CoL, int outSplit,
    const float* __restrict__ resid, const float* __restrict__ lnG,
    const float* __restrict__ lnB, float* __restrict__ rawOut)
{
    extern __shared__ char sm[];
    const uint32_t sb = smem_u32(sm);
    const int tid = threadIdx.x, wid = tid >> 5, lane = tid & 31;
    const int m0 = blockIdx.y * 128;
    const int mrow0 = (wid & 3) * 32;
    const int ncol0 = (wid >> 2) * 64;
    const int rowoff = ((lane >> 3) & 1) * 8 + (lane & 7);
    const int coloff = (lane >> 4) * 8;

    const int lr0 = tid >> 2, lg0 = (tid & 3) << 3;
    const int lr1 = (tid + 256) >> 2, lg1 = ((tid + 256) & 3) << 3;
    int mm0 = m0 + lr0; if (mm0 >= M) mm0 = M - 1;
    int mm1 = m0 + lr1; if (mm1 >= M) mm1 = M - 1;

    auto issue_chunk = [&](int c) {
        const uint32_t bb = sb + (uint32_t)(c % 3) * BUFSTR;
        const int k0 = c << 5;
#pragma unroll
        for (int it = 0; it < 2; ++it) {
            int r = it ? lr1 : lr0, g = it ? lg1 : lg0;
            int mm = it ? mm1 : mm0;
            int kg = k0 + g;
            uint32_t off = (uint32_t)(r * PITCH + g * 2);
            cp16(bb + off, AhG + (size_t)mm * K + kg);
            cp16(bb + ARR + off, AlG + (size_t)mm * K + kg);
        }
#pragma unroll
        for (int it = 0; it < 2; ++it) {
            int r = it ? lr1 : lr0, g = it ? lg1 : lg0;
            size_t so = (size_t)r * K + k0 + g;
            uint32_t off = (uint32_t)(r * PITCH + g * 2);
            cp16(bb + 2 * ARR + off, BT + so);
        }
        CP_COMMIT();
    };

    float acc[2][8][4];
#pragma unroll
    for (int i = 0; i < 2; i++)
#pragma unroll
        for (int j = 0; j < 8; j++)
#pragma unroll
            for (int q = 0; q < 4; q++) acc[i][j][q] = 0.f;

    const int nCh = K >> 5;
    issue_chunk(0);
    if (nCh > 1) issue_chunk(1);
    for (int c = 0; c < nCh; ++c) {
        if (c + 1 < nCh) CP_WAIT1();
        else CP_WAIT0();
        __syncthreads();
        const uint32_t bb = sb + (uint32_t)(c % 3) * BUFSTR;
#pragma unroll
        for (int ks = 0; ks < 2; ++ks) {
            const uint32_t kb = (uint32_t)((ks * 16 + coloff) * 2);
            uint32_t ah[2][4], al[2][4];
#pragma unroll
            for (int ma = 0; ma < 2; ++ma) {
                uint32_t ro = (uint32_t)((mrow0 + ma * 16 + rowoff) * PITCH) + kb;
                ldsm4(ah[ma], bb + ro);
                ldsm4(al[ma], bb + ARR + ro);
            }
            uint32_t bh[8][2];
#pragma unroll
            for (int ng = 0; ng < 4; ++ng) {
                uint32_t ro = (uint32_t)((ncol0 + ng * 16 + rowoff) * PITCH) + kb;
                uint32_t t[4];
                ldsm4(t, bb + 2 * ARR + ro);
                bh[2 * ng][0] = t[0]; bh[2 * ng][1] = t[2];
                bh[2 * ng + 1][0] = t[1]; bh[2 * ng + 1][1] = t[3];
            }
#pragma unroll
            for (int ma = 0; ma < 2; ++ma)
#pragma unroll
                for (int na = 0; na < 8; ++na) mma16816(acc[ma][na], ah[ma], bh[na]);
#pragma unroll
            for (int ma = 0; ma < 2; ++ma)
#pragma unroll
                for (int na = 0; na < 8; ++na) mma16816(acc[ma][na], al[ma], bh[na]);
        }
        if (c + 2 < nCh) issue_chunk(c + 2);
    }

    // ---- fused LN epilogue ----
    const int qr = lane >> 2, qc = (lane & 3) * 2;
    float (*pS)[2] = (float(*)[2])(sm + SM_PART);
    float (*pQ)[2] = (float(*)[2])(sm + SM_PART + 1024);
    const int nh = wid >> 2;
    float s[2][2] = {{0.f, 0.f}, {0.f, 0.f}};
    float q[2][2] = {{0.f, 0.f}, {0.f, 0.f}};
#pragma unroll
    for (int ma = 0; ma < 2; ++ma) {
        int mA = m0 + mrow0 + ma * 16 + qr;
        int mB = mA + 8;
#pragma unroll
        for (int na = 0; na < 8; ++na) {
            int n = ncol0 + na * 8 + qc;
            float pA0 = acc[ma][na][0] + bias[n];
            float pA1 = acc[ma][na][1] + bias[n + 1];
            float pB0 = acc[ma][na][2] + bias[n];
            float pB1 = acc[ma][na][3] + bias[n + 1];
            float oA0 = 0.f, oA1 = 0.f, oB0 = 0.f, oB1 = 0.f;
            if (mA < M) {
                if (rawOut) *(float2*)(rawOut + (size_t)mA * 128 + n) = make_float2(pA0, pA1);
                oA0 = pA0 + resid[(size_t)mA * 128 + n];
                oA1 = pA1 + resid[(size_t)mA * 128 + n + 1];
            }
            if (mB < M) {
                if (rawOut) *(float2*)(rawOut + (size_t)mB * 128 + n) = make_float2(pB0, pB1);
                oB0 = pB0 + resid[(size_t)mB * 128 + n];
                oB1 = pB1 + resid[(size_t)mB * 128 + n + 1];
            }
            acc[ma][na][0] = oA0; acc[ma][na][1] = oA1;
            acc[ma][na][2] = oB0; acc[ma][na][3] = oB1;
            s[ma][0] += oA0 + oA1; q[ma][0] += oA0 * oA0 + oA1 * oA1;
            s[ma][1] += oB0 + oB1; q[ma][1] += oB0 * oB0 + oB1 * oB1;
        }
    }
#pragma unroll
    for (int ma = 0; ma < 2; ++ma)
#pragma unroll
        for (int g2 = 0; g2 < 2; ++g2) {
            s[ma][g2] += __shfl_xor_sync(0xffffffffu, s[ma][g2], 1);
            s[ma][g2] += __shfl_xor_sync(0xffffffffu, s[ma][g2], 2);
            q[ma][g2] += __shfl_xor_sync(0xffffffffu, q[ma][g2], 1);
            q[ma][g2] += __shfl_xor_sync(0xffffffffu, q[ma][g2], 2);
        }
    __syncthreads();
    if ((lane & 3) == 0) {
#pragma unroll
        for (int ma = 0; ma < 2; ++ma) {
            int r = mrow0 + ma * 16 + qr;
            pS[r][nh] = s[ma][0]; pQ[r][nh] = q[ma][0];
            pS[r + 8][nh] = s[ma][1]; pQ[r + 8][nh] = q[ma][1];
        }
    }
    __syncthreads();
    float mean_[2][2], rstd_[2][2];
#pragma unroll
    for (int ma = 0; ma < 2; ++ma)
#pragma unroll
        for (int g2 = 0; g2 < 2; ++g2) {
            int r = mrow0 + ma * 16 + g2 * 8 + qr;
            float mu = (pS[r][0] + pS[r][1]) * (1.0f / 128.0f);
            float var = (pQ[r][0] + pQ[r][1]) * (1.0f / 128.0f) - mu * mu;
            mean_[ma][g2] = mu;
            rstd_[ma][g2] = rsqrtf(var + 1e-5f);
        }
#pragma unroll
    for (int ma = 0; ma < 2; ++ma) {
        int mA = m0 + mrow0 + ma * 16 + qr;
        int mB = mA + 8;
#pragma unroll
        for (int na = 0; na < 8; ++na) {
            int n = ncol0 + na * 8 + qc;
            float g0 = lnG[n], g1 = lnG[n + 1], b0 = lnB[n], b1 = lnB[n + 1];
            if (mA < M) {
                float yA0 = (acc[ma][na][0] - mean_[ma][0]) * rstd_[ma][0] * g0 + b0;
                float yA1 = (acc[ma][na][1] - mean_[ma][0]) * rstd_[ma][0] * g1 + b1;
                *(float2*)(Cout + (size_t)mA * 128 + n) = make_float2(yA0, yA1);
                if (outSplit) {
                    __half h0, l0, h1, l1;
                    split2h(yA0, h0, l0); split2h(yA1, h1, l1);
                    *(uint32_t*)(CoH + (size_t)mA * 128 + n) = packh(h0, h1);
                    *(uint32_t*)(CoL + (size_t)mA * 128 + n) = packh(l0, l1);
                }
            }
            if (mB < M) {
                float yB0 = (acc[ma][na][2] - mean_[ma][1]) * rstd_[ma][1] * g0 + b0;
                float yB1 = (acc[ma][na][3] - mean_[ma][1]) * rstd_[ma][1] * g1 + b1;
                *(float2*)(Cout + (size_t)mB * 128 + n) = make_float2(yB0, yB1);
                if (outSplit) {
                    __half h0, l0, h1, l1;
                    split2h(yB0, h0, l0); split2h(yB1, h1, l1);
                    *(uint32_t*)(CoH + (size_t)mB * 128 + n) = packh(h0, h1);
                    *(uint32_t*)(CoL + (size_t)mB * 128 + n) = packh(l0, l1);
                }
            }
        }
    }
}

// ---------------- weight transpose to fp16 ----------------
struct TEnt { const float* src; int dstOff; int K; int N; };
struct TTab { TEnt e[26]; };
__global__ void tsplit_k(TTab tab) {
    TEnt E = tab.e[blockIdx.y];
    int i = blockIdx.x * 256 + threadIdx.x;
    int total = E.K * E.N;
    if (i >= total) return;
    int k = i / E.N, n = i % E.N;
    g_wT[E.dstOff + (size_t)n * E.K + k] = __float2half_rn(E.src[i]);
}

// ---------------- setup ----------------
__global__ void embed_k(const int* __restrict__ seq, const float* __restrict__ emb) {
    int i = blockIdx.x * 256 + threadIdx.x;
    if (i < Nn * 128) {
        int nidx = i >> 7, d = i & 127;
        float x = emb[seq[nidx] * 128 + d];
        g_nodes[i] = x;
        __half h, l;
        split2h(x, h, l);
        g_nodesH[i] = h; g_nodesL[i] = l;
    }
}
__global__ void rbf_k(const float* __restrict__ dist, const float* __restrict__ W,
                      const float* __restrict__ b) {
    __shared__ float r[16];
    int e = blockIdx.x;
    int t = threadIdx.x;
    if (t < 16) {
        float mu = 2.0f + (20.0f / 15.0f) * (float)t;
        float x = (dist[e] - mu) * (1.0f / 1.25f);
        r[t] = expf(-x * x) + 1e-8f;
    }
    __syncthreads();
    float s = b[t];
#pragma unroll
    for (int j = 0; j < 16; j++) s += r[j] * W[j * 128 + t];
    long long i = (long long)e * 128 + t;
    g_eattr[i] = s;
    __half h, l;
    split2h(s, h, l);
    g_eatH[i] = h; g_eatL[i] = l;
}

// ---------------- CSR ----------------
__global__ void zero_cnt_k() {
    int i = blockIdx.x * 256 + threadIdx.x;
    if (i < Nn) g_cnt[i] = 0;
}
__global__ void count_k(const int* __restrict__ snk) {
    int e = blockIdx.x * 256 + threadIdx.x;
    if (e < Ee) atomicAdd(&g_cnt[snk[e]], 1);
}
__global__ void __launch_bounds__(1024) scan_k() {
    __shared__ int s[1024];
    int t = threadIdx.x;
    const int CH = (Nn + 1023) / 1024;
    int st = t * CH;
    int en = st + CH; if (en > Nn) en = Nn; if (st > Nn) st = Nn;
    int loc = 0;
    for (int i = st; i < en; i++) loc += g_cnt[i];
    s[t] = loc;
    __syncthreads();
    for (int d = 1; d < 1024; d <<= 1) {
        int v = (t >= d) ? s[t - d] : 0;
        __syncthreads();
        s[t] += v;
        __syncthreads();
    }
    int run = (t == 0) ? 0 : s[t - 1];
    for (int i = st; i < en; i++) {
        g_off[i] = run; g_cur[i] = run; run += g_cnt[i];
    }
    if (t == 1023) g_off[Nn] = s[1023];
}
__global__ void place_k(const int* __restrict__ snk) {
    int e = blockIdx.x * 256 + threadIdx.x;
    if (e < Ee) {
        int p = atomicAdd(&g_cur[snk[e]], 1);
        g_csr[p] = e;
    }
}

// ---------------- per-node softmax + aggregation ----------------
__global__ void __launch_bounds__(128) agg_k() {
    __shared__ float red[4][128];
    int n = blockIdx.x, t = threadIdx.x;
    int beg = g_off[n], end = g_off[n + 1];
    const float4* sc4 = (const float4*)g_scores;

    float mx[4] = {-1e30f, -1e30f, -1e30f, -1e30f};
    for (int i = beg + t; i < end; i += 128) {
        float4 s = sc4[g_csr[i]];
        mx[0] = fmaxf(mx[0], s.x); mx[1] = fmaxf(mx[1], s.y);
        mx[2] = fmaxf(mx[2], s.z); mx[3] = fmaxf(mx[3], s.w);
    }
#pragma unroll
    for (int h = 0; h < 4; h++) red[h][t] = mx[h];
    __syncthreads();
    for (int s = 64; s > 0; s >>= 1) {
        if (t < s)
#pragma unroll
            for (int h = 0; h < 4; h++) red[h][t] = fmaxf(red[h][t], red[h][t + s]);
        __syncthreads();
    }
    float mxf[4];
#pragma unroll
    for (int h = 0; h < 4; h++) mxf[h] = red[h][0];
    __syncthreads();

    float sm[4] = {0.f, 0.f, 0.f, 0.f};
    for (int i = beg + t; i < end; i += 128) {
        float4 s = sc4[g_csr[i]];
        sm[0] += expf(s.x - mxf[0]) + 1e-12f;
        sm[1] += expf(s.y - mxf[1]) + 1e-12f;
        sm[2] += expf(s.z - mxf[2]) + 1e-12f;
        sm[3] += expf(s.w - mxf[3]) + 1e-12f;
    }
#pragma unroll
    for (int h = 0; h < 4; h++) red[h][t] = sm[h];
    __syncthreads();
    for (int s = 64; s > 0; s >>= 1) {
        if (t < s)
#pragma unroll
            for (int h = 0; h < 4; h++) red[h][t] += red[h][t + s];
        __syncthreads();
    }
    float nrm[4];
#pragma unroll
    for (int h = 0; h < 4; h++) nrm[h] = red[h][0];

    float acc[4] = {0.f, 0.f, 0.f, 0.f};
    for (int i = beg; i < end; i++) {
        int e = g_csr[i];
        float4 s = sc4[e];
        float a0 = expf(s.x - mxf[0]) / nrm[0];
        float a1 = expf(s.y - mxf[1]) / nrm[1];
        float a2 = expf(s.z - mxf[2]) / nrm[2];
        float a3 = expf(s.w - mxf[3]) / nrm[3];
        float v = g_nupd[(long long)e * 128 + t];
        acc[0] += a0 * v; acc[1] += a1 * v; acc[2] += a2 * v; acc[3] += a3 * v;
    }
    long long base = (long long)n * 512;
#pragma unroll
    for (int h = 0; h < 4; h++) {
        __half hh, ll;
        split2h(acc[h], hh, ll);
        g_aggH[base + h * 128 + t] = hh;
        g_aggL[base + h * 128 + t] = ll;
    }
}

// ---------------- host ----------------
extern "C" void kernel_launch(void* const* d_in, const int* in_sizes, int n_in,
                              void* d_out, int out_size) {
    const int* seq = (const int*)d_in[0];
    const int* eidx = (const int*)d_in[1];
    const int* srcI = eidx;
    const int* snkI = eidx + Ee;
    const float* dist = (const float*)d_in[2];
    const float* seq_embed = (const float*)d_in[3];
    const float* edge_lin_W = (const float*)d_in[4];
    const float* edge_lin_b = (const float*)d_in[5];
    const float* aW_W = (const float*)d_in[6];
    const float* aW_b = (const float*)d_in[7];
    const float* aA_W = (const float*)d_in[8];
    const float* aA_b = (const float*)d_in[9];
    const float* nmlp_W1 = (const float*)d_in[10];
    const float* nmlp_b1 = (const float*)d_in[11];
    const float* nmlp_W2 = (const float*)d_in[12];
    const float* nmlp_b2 = (const float*)d_in[13];
    const float* nmlp_W3 = (const float*)d_in[14];
    const float* nmlp_b3 = (const float*)d_in[15];
    const float* dmlp_W1 = (const float*)d_in[16];
    const float* dmlp_b1 = (const float*)d_in[17];
    const float* dmlp_W2 = (const float*)d_in[18];
    const float* dmlp_b2 = (const float*)d_in[19];
    const float* emlp_W1 = (const float*)d_in[20];
    const float* emlp_b1 = (const float*)d_in[21];
    const float* emlp_W2 = (const float*)d_in[22];
    const float* emlp_b2 = (const float*)d_in[23];
    const float* emlp_W3 = (const float*)d_in[24];
    const float* emlp_b3 = (const float*)d_in[25];
    const float* aggr_W = (const float*)d_in[26];
    const float* aggr_b = (const float*)d_in[27];
    const float* n1_g = (const float*)d_in[28];
    const float* n1_b = (const float*)d_in[29];
    const float* e_g = (const float*)d_in[30];
    const float* e_b = (const float*)d_in[31];

    float *p_nodes, *p_eattr, *p_nupd, *p_scores, *p_upd;
    __half *pW, *pNh, *pNl, *pEh, *pEl, *pB1h, *pB1l, *pB2h, *pB2l, *pAgh, *pAgl;
    cudaGetSymbolAddress((void**)&p_nodes, g_nodes);
    cudaGetSymbolAddress((void**)&p_eattr, g_eattr);
    cudaGetSymbolAddress((void**)&p_nupd, g_nupd);
    cudaGetSymbolAddress((void**)&p_scores, g_scores);
    cudaGetSymbolAddress((void**)&p_upd, g_upd);
    cudaGetSymbolAddress((void**)&pW, g_wT);
    cudaGetSymbolAddress((void**)&pNh, g_nodesH);
    cudaGetSymbolAddress((void**)&pNl, g_nodesL);
    cudaGetSymbolAddress((void**)&pEh, g_eatH);
    cudaGetSymbolAddress((void**)&pEl, g_eatL);
    cudaGetSymbolAddress((void**)&pB1h, g_b1H);
    cudaGetSymbolAddress((void**)&pB1l, g_b1L);
    cudaGetSymbolAddress((void**)&pB2h, g_b2H);
    cudaGetSymbolAddress((void**)&pB2l, g_b2L);
    cudaGetSymbolAddress((void**)&pAgh, g_aggH);
    cudaGetSymbolAddress((void**)&pAgl, g_aggL);

    cudaFuncSetAttribute(gemm_tc, cudaFuncAttributeMaxDynamicSharedMemorySize, SM_TOTAL);
    cudaFuncSetAttribute(gemm_ln, cudaFuncAttributeMaxDynamicSharedMemorySize, SM_TOTAL_LN);

    TTab tab;
    {
        int idx = 0;
        for (int l = 0; l < 2; l++) {
            int lb = l * WT_LAYER;
            for (int h = 0; h < 4; h++)
                tab.e[idx++] = { aW_W + (size_t)(l * 4 + h) * 384 * 128, lb + h * 49152, 384, 128 };
            tab.e[idx++] = { nmlp_W1 + (size_t)l * 384 * 128, lb + 196608, 384, 128 };
            tab.e[idx++] = { nmlp_W2 + (size_t)l * 128 * 128, lb + 245760, 128, 128 };
            tab.e[idx++] = { nmlp_W3 + (size_t)l * 128 * 128, lb + 262144, 128, 128 };
            tab.e[idx++] = { aggr_W + (size_t)l * 512 * 128, lb + 278528, 512, 128 };
            tab.e[idx++] = { dmlp_W1 + (size_t)l * 128 * 512, lb + 344064, 128, 512 };
            tab.e[idx++] = { dmlp_W2 + (size_t)l * 512 * 128, lb + 409600, 512, 128 };
            tab.e[idx++] = { emlp_W1 + (size_t)l * 384 * 128, lb + 475136, 384, 128 };
            tab.e[idx++] = { emlp_W2 + (size_t)l * 128 * 128, lb + 524288, 128, 128 };
            tab.e[idx++] = { emlp_W3 + (size_t)l * 128 * 128, lb + 540672, 128, 128 };
        }
    }

    auto gemm = [&](int M, int K, int nTile, int zDim,
                    const __half* Ah, const __half* Al, long long wOff,
                    const float* bias, float* Cp, __half* CoH, __half* CoL,
                    int ldc, int act, int feat, int osplit,
                    const float* aAv, const float* aAb) {
        dim3 g(nTile, (M + 127) / 128, zDim);
        gemm_tc<<<g, 256, SM_TOTAL>>>(M, K, Ah, Al, pW + wOff, bias, Cp, CoH, CoL, ldc,
                                      act, feat, osplit, pNh, pNl, pEh, pEl, srcI, snkI, aAv, aAb);
    };
    auto gemmLN = [&](int M, int K, const __half* Ah, const __half* Al, long long wOff,
                      const float* bias, float* Cp, __half* CoH, __half* CoL, int osplit,
                      const float* resid, const float* lnG, const float* lnB, float* rawOut) {
        dim3 g(1, (M + 127) / 128, 1);
        gemm_ln<<<g, 256, SM_TOTAL_LN>>>(M, K, Ah, Al, pW + wOff, bias, Cp, CoH, CoL, osplit,
                                         resid, lnG, lnB, rawOut);
    };

    tsplit_k<<<dim3(256, 26), 256>>>(tab);
    embed_k<<<(Nn * 128 + 255) / 256, 256>>>(seq, seq_embed);
    rbf_k<<<Ee, 128>>>(dist, edge_lin_W, edge_lin_b);
    zero_cnt_k<<<(Nn + 255) / 256, 256>>>();
    count_k<<<(Ee + 255) / 256, 256>>>(snkI);
    scan_k<<<1, 1024>>>();
    place_k<<<(Ee + 255) / 256, 256>>>(snkI);

    float* outNodes = (float*)d_out;
    float* outEattr = (float*)d_out + (long long)Nn * 128;

    for (int l = 0; l < 2; l++) {
        long long lb = (long long)l * WT_LAYER;
        // attention scores
        gemm(Ee, Cc, 1, 4, nullptr, nullptr, lb + 0, aW_b + l * 512,
             p_scores, nullptr, nullptr, 0, 2, 1, 0, aA_W + l * 512, aA_b + l * 4);
        // node-message MLP
        gemm(Ee, Cc, 1, 1, nullptr, nullptr, lb + 196608, nmlp_b1 + l * 128,
             nullptr, pB1h, pB1l, 128, 1, 1, 1, nullptr, nullptr);
        gemm(Ee, 128, 1, 1, pB1h, pB1l, lb + 245760, nmlp_b2 + l * 128,
             nullptr, pB2h, pB2l, 128, 1, 0, 1, nullptr, nullptr);
        gemm(Ee, 128, 1, 1, pB2h, pB2l, lb + 262144, nmlp_b3 + l * 128,
             p_nupd, nullptr, nullptr, 128, 0, 0, 0, nullptr, nullptr);
        agg_k<<<Nn, 128>>>();
        // aggr GEMM + fused LN (separate kernel): upd raw -> p_upd; nodes = LN(nodes + upd)
        gemmLN(Nn, 512, pAgh, pAgl, lb + 278528, aggr_b + l * 128,
               p_nodes, pNh, pNl, 1, p_nodes, n1_g + l * 128, n1_b + l * 128, p_upd);
        // dense MLP; dmlp2 + fused LN: nodes = LN(dense + upd)
        gemm(Nn, 128, 4, 1, pNh, pNl, lb + 344064, dmlp_b1 + l * 512,
             nullptr, pB1h, pB1l, 512, 1, 0, 1, nullptr, nullptr);
        gemmLN(Nn, 512, pB1h, pB1l, lb + 409600, dmlp_b2 + l * 128,
               l == 1 ? outNodes : p_nodes, pNh, pNl, 1,
               p_upd, n1_g + l * 128, n1_b + l * 128, nullptr);
        // edge MLP; emlp3 + fused LN: eattr = LN(eattr + eu)
        gemm(Ee, Cc, 1, 1, nullptr, nullptr, lb + 475136, emlp_b1 + l * 128,
             nullptr, pB1h, pB1l, 128, 1, 1, 1, nullptr, nullptr);
        gemm(Ee, 128, 1, 1, pB1h, pB1l, lb + 524288, emlp_b2 + l * 128,
             nullptr, pB2h, pB2l, 128, 1, 0, 1, nullptr, nullptr);
        gemmLN(Ee, 128, pB2h, pB2l, lb + 540672, emlp_b3 + l * 128,
               l == 1 ? outEattr : p_eattr, pEh, pEl, l == 0 ? 1 : 0,
               p_eattr, e_g + l * 128, e_b + l * 128, nullptr);
    }
}

// round 17
// speedup vs baseline: 1.2621x; 1.0597x over previous
#include <cuda_runtime.h>
#include <cuda_fp16.h>
#include <math.h>
#include <stdint.h>

#define Nn 6000
#define Ee 120000
#define Dd 128
#define Hh 4
#define Cc 384

// ---------------- scratch (device globals) ----------------
__device__ __align__(16) float g_nodes[Nn * Dd];
__device__ __align__(16) float g_eattr[Ee * Dd];
__device__ __align__(16) float g_nupd[Ee * Dd];
__device__ __align__(16) float g_scores[Ee * Hh];
__device__ __align__(16) float g_upd[Nn * Dd];
__device__ __align__(16) __half g_nodesH[Nn * Dd], g_nodesL[Nn * Dd];
__device__ __align__(16) __half g_eatH[Ee * Dd], g_eatL[Ee * Dd];
__device__ __align__(16) __half g_b1H[Ee * Dd], g_b1L[Ee * Dd];
__device__ __align__(16) __half g_b2H[Ee * Dd], g_b2L[Ee * Dd];
__device__ __align__(16) __half g_aggH[Nn * 4 * Dd], g_aggL[Nn * 4 * Dd];
__device__ int g_cnt[Nn];
__device__ int g_off[Nn + 1];
__device__ int g_cur[Nn];
__device__ int g_csr[Ee];
#define WT_LAYER 557056
__device__ __align__(16) __half g_wT[2 * WT_LAYER];

__device__ __forceinline__ float gelu_f(float x) {
    return 0.5f * x * (1.0f + erff(x * 0.70710678118654752f));
}
__device__ __forceinline__ uint32_t smem_u32(const void* p) {
    uint32_t a;
    asm("{ .reg .u64 t; cvta.to.shared.u64 t, %1; cvt.u32.u64 %0, t; }" : "=r"(a) : "l"(p));
    return a;
}
__device__ __forceinline__ void ldsm4(uint32_t* r, uint32_t addr) {
    asm volatile("ldmatrix.sync.aligned.m8n8.x4.shared.b16 {%0,%1,%2,%3}, [%4];"
                 : "=r"(r[0]), "=r"(r[1]), "=r"(r[2]), "=r"(r[3]) : "r"(addr));
}
__device__ __forceinline__ void mma16816(float* d, const uint32_t* a, const uint32_t* b) {
    asm volatile("mma.sync.aligned.m16n8k16.row.col.f32.f16.f16.f32 "
                 "{%0,%1,%2,%3}, {%4,%5,%6,%7}, {%8,%9}, {%0,%1,%2,%3};"
                 : "+f"(d[0]), "+f"(d[1]), "+f"(d[2]), "+f"(d[3])
                 : "r"(a[0]), "r"(a[1]), "r"(a[2]), "r"(a[3]), "r"(b[0]), "r"(b[1]));
}
__device__ __forceinline__ void split2h(float x, __half& h, __half& l) {
    h = __float2half_rn(x);
    l = __float2half_rn(x - __half2float(h));
}
__device__ __forceinline__ uint32_t packh(__half a, __half b) {
    return ((uint32_t)__half_as_ushort(b) << 16) | __half_as_ushort(a);
}
__device__ __forceinline__ void cp16(uint32_t saddr, const void* g) {
    asm volatile("cp.async.ca.shared.global [%0], [%1], 16;" :: "r"(saddr), "l"(g));
}
#define CP_COMMIT() asm volatile("cp.async.commit_group;" ::: "memory")
#define CP_WAIT1()  asm volatile("cp.async.wait_group 1;" ::: "memory")
#define CP_WAIT0()  asm volatile("cp.async.wait_group 0;" ::: "memory")

#define PITCH 80
#define ARR 10240
#define BUFSTR 30720
#define SM_PART 92160
#define SM_TOTAL 93184
#define SM_TOTAL_LN 94208

// ---------------- generic GEMM (act: 0 none, 1 gelu, 2 score-or-fused) ----------------
// act==2: z<4 -> score head epilogue; z==4 -> gelu + split epilogue with bias4 (fused nmlp1)
__global__ void __launch_bounds__(256) gemm_tc(
    int M, int K,
    const __half* __restrict__ AhG, const __half* __restrict__ AlG,
    const __half* __restrict__ BT,
    const float* __restrict__ bias,
    float* __restrict__ Cout,
    __half* __restrict__ CoH, __half* __restrict__ CoL, int ldc,
    int act, int featMode, int outSplit,
    const __half* __restrict__ ndH, const __half* __restrict__ ndL,
    const __half* __restrict__ eaH, const __half* __restrict__ eaL,
    const int* __restrict__ srcI, const int* __restrict__ snkI,
    const float* __restrict__ aAv, const float* __restrict__ aAb,
    const float* __restrict__ bias4)
{
    extern __shared__ char sm[];
    const uint32_t sb = smem_u32(sm);
    const int tid = threadIdx.x, wid = tid >> 5, lane = tid & 31;
    const int m0 = blockIdx.y * 128, n0 = blockIdx.x * 128, z = blockIdx.z;
    if (act == 2) {
        BT += (size_t)z * K * 128;          // weights contiguous: heads 0-3 then nmlp1
        if (z < 4) { bias += z * 128; aAv += z * 128; }
        else bias = bias4;
    }
    const int mrow0 = (wid & 3) * 32;
    const int ncol0 = (wid >> 2) * 64;
    const int rowoff = ((lane >> 3) & 1) * 8 + (lane & 7);
    const int coloff = (lane >> 4) * 8;

    const int lr0 = tid >> 2, lg0 = (tid & 3) << 3;
    const int lr1 = (tid + 256) >> 2, lg1 = ((tid + 256) & 3) << 3;

    int mm0 = m0 + lr0; if (mm0 >= M) mm0 = M - 1;
    int mm1 = m0 + lr1; if (mm1 >= M) mm1 = M - 1;
    int s0 = 0, t0 = 0, s1 = 0, t1 = 0;
    if (featMode) {
        s0 = srcI[mm0]; t0 = snkI[mm0];
        s1 = srcI[mm1]; t1 = snkI[mm1];
    }

    auto issue_chunk = [&](int c) {
        const uint32_t bb = sb + (uint32_t)(c % 3) * BUFSTR;
        const int k0 = c << 5;
#pragma unroll
        for (int it = 0; it < 2; ++it) {
            int r = it ? lr1 : lr0, g = it ? lg1 : lg0;
            int mm = it ? mm1 : mm0;
            int kg = k0 + g;
            const __half *ph, *pl;
            if (!featMode) { ph = AhG + (size_t)mm * K + kg; pl = AlG + (size_t)mm * K + kg; }
            else if (kg < 128) { int s = it ? s1 : s0; ph = ndH + (size_t)s * 128 + kg; pl = ndL + (size_t)s * 128 + kg; }
            else if (kg < 256) { int s = it ? t1 : t0; ph = ndH + (size_t)s * 128 + (kg - 128); pl = ndL + (size_t)s * 128 + (kg - 128); }
            else { ph = eaH + (size_t)mm * 128 + (kg - 256); pl = eaL + (size_t)mm * 128 + (kg - 256); }
            uint32_t off = (uint32_t)(r * PITCH + g * 2);
            cp16(bb + off, ph);
            cp16(bb + ARR + off, pl);
        }
#pragma unroll
        for (int it = 0; it < 2; ++it) {
            int r = it ? lr1 : lr0, g = it ? lg1 : lg0;
            size_t so = (size_t)(n0 + r) * K + k0 + g;
            uint32_t off = (uint32_t)(r * PITCH + g * 2);
            cp16(bb + 2 * ARR + off, BT + so);
        }
        CP_COMMIT();
    };

    float acc[2][8][4];
#pragma unroll
    for (int i = 0; i < 2; i++)
#pragma unroll
        for (int j = 0; j < 8; j++)
#pragma unroll
            for (int q = 0; q < 4; q++) acc[i][j][q] = 0.f;

    const int nCh = K >> 5;
    issue_chunk(0);
    if (nCh > 1) issue_chunk(1);
    for (int c = 0; c < nCh; ++c) {
        if (c + 1 < nCh) CP_WAIT1();
        else CP_WAIT0();
        __syncthreads();
        const uint32_t bb = sb + (uint32_t)(c % 3) * BUFSTR;
#pragma unroll
        for (int ks = 0; ks < 2; ++ks) {
            const uint32_t kb = (uint32_t)((ks * 16 + coloff) * 2);
            uint32_t ah[2][4], al[2][4];
#pragma unroll
            for (int ma = 0; ma < 2; ++ma) {
                uint32_t ro = (uint32_t)((mrow0 + ma * 16 + rowoff) * PITCH) + kb;
                ldsm4(ah[ma], bb + ro);
                ldsm4(al[ma], bb + ARR + ro);
            }
            uint32_t bh[8][2];
#pragma unroll
            for (int ng = 0; ng < 4; ++ng) {
                uint32_t ro = (uint32_t)((ncol0 + ng * 16 + rowoff) * PITCH) + kb;
                uint32_t t[4];
                ldsm4(t, bb + 2 * ARR + ro);
                bh[2 * ng][0] = t[0]; bh[2 * ng][1] = t[2];
                bh[2 * ng + 1][0] = t[1]; bh[2 * ng + 1][1] = t[3];
            }
#pragma unroll
            for (int ma = 0; ma < 2; ++ma)
#pragma unroll
                for (int na = 0; na < 8; ++na) mma16816(acc[ma][na], ah[ma], bh[na]);
#pragma unroll
            for (int ma = 0; ma < 2; ++ma)
#pragma unroll
                for (int na = 0; na < 8; ++na) mma16816(acc[ma][na], al[ma], bh[na]);
        }
        if (c + 2 < nCh) issue_chunk(c + 2);
    }

    const int qr = lane >> 2, qc = (lane & 3) * 2;
    if (act == 2 && z < 4) {
        float (*part)[2] = (float(*)[2])(sm + SM_PART);
        const int nh = wid >> 2;
        float s[2][2] = {{0.f, 0.f}, {0.f, 0.f}};
#pragma unroll
        for (int ma = 0; ma < 2; ++ma)
#pragma unroll
            for (int na = 0; na < 8; ++na) {
                int n = ncol0 + na * 8 + qc;
#pragma unroll
                for (int j = 0; j < 2; ++j) {
                    float v0 = acc[ma][na][j] + bias[n + j];
                    v0 = v0 > 0.f ? v0 : 0.2f * v0;
                    s[ma][0] += v0 * aAv[n + j];
                    float v1 = acc[ma][na][2 + j] + bias[n + j];
                    v1 = v1 > 0.f ? v1 : 0.2f * v1;
                    s[ma][1] += v1 * aAv[n + j];
                }
            }
#pragma unroll
        for (int ma = 0; ma < 2; ++ma)
#pragma unroll
            for (int g = 0; g < 2; ++g) {
                s[ma][g] += __shfl_xor_sync(0xffffffffu, s[ma][g], 1);
                s[ma][g] += __shfl_xor_sync(0xffffffffu, s[ma][g], 2);
            }
        __syncthreads();
        if ((lane & 3) == 0) {
#pragma unroll
            for (int ma = 0; ma < 2; ++ma) {
                part[mrow0 + ma * 16 + qr][nh] = s[ma][0];
                part[mrow0 + ma * 16 + 8 + qr][nh] = s[ma][1];
            }
        }
        __syncthreads();
        if (tid < 128) {
            int m = m0 + tid;
            if (m < M) Cout[(size_t)m * 4 + z] = part[tid][0] + part[tid][1] + aAb[z];
        }
        return;
    }
    const int actEff = (act == 2) ? 1 : act;           // z==4: gelu
    const int osEff = (act == 2) ? 1 : outSplit;       // z==4: split out
#pragma unroll
    for (int ma = 0; ma < 2; ++ma) {
        int mA = m0 + mrow0 + ma * 16 + qr;
        int mB = mA + 8;
#pragma unroll
        for (int na = 0; na < 8; ++na) {
            int n = n0 + ncol0 + na * 8 + qc;
            float2 oA, oB;
            oA.x = acc[ma][na][0] + bias[n];
            oA.y = acc[ma][na][1] + bias[n + 1];
            oB.x = acc[ma][na][2] + bias[n];
            oB.y = acc[ma][na][3] + bias[n + 1];
            if (actEff == 1) {
                oA.x = gelu_f(oA.x); oA.y = gelu_f(oA.y);
                oB.x = gelu_f(oB.x); oB.y = gelu_f(oB.y);
            }
            if (osEff) {
                __half h0, l0, h1, l1;
                if (mA < M) {
                    split2h(oA.x, h0, l0); split2h(oA.y, h1, l1);
                    *(uint32_t*)(CoH + (size_t)mA * ldc + n) = packh(h0, h1);
                    *(uint32_t*)(CoL + (size_t)mA * ldc + n) = packh(l0, l1);
                }
                if (mB < M) {
                    split2h(oB.x, h0, l0); split2h(oB.y, h1, l1);
                    *(uint32_t*)(CoH + (size_t)mB * ldc + n) = packh(h0, h1);
                    *(uint32_t*)(CoL + (size_t)mB * ldc + n) = packh(l0, l1);
                }
            } else {
                if (mA < M) *(float2*)(Cout + (size_t)mA * ldc + n) = oA;
                if (mB < M) *(float2*)(Cout + (size_t)mB * ldc + n) = oB;
            }
        }
    }
}

// ---------------- GEMM + fused LayerNorm kernel (N == 128, no featMode) ----------------
__global__ void __launch_bounds__(256) gemm_ln(
    int M, int K,
    const __half* __restrict__ AhG, const __half* __restrict__ AlG,
    const __half* __restrict__ BT,
    const float* __restrict__ bias,
    float* __restrict__ Cout,
    __half* __restrict__ CoH, __half* __restrict__ CoL, int outSplit,
    const float* __restrict__ resid, const float* __restrict__ lnG,
    const float* __restrict__ lnB, float* __restrict__ rawOut)
{
    extern __shared__ char sm[];
    const uint32_t sb = smem_u32(sm);
    const int tid = threadIdx.x, wid = tid >> 5, lane = tid & 31;
    const int m0 = blockIdx.y * 128;
    const int mrow0 = (wid & 3) * 32;
    const int ncol0 = (wid >> 2) * 64;
    const int rowoff = ((lane >> 3) & 1) * 8 + (lane & 7);
    const int coloff = (lane >> 4) * 8;

    const int lr0 = tid >> 2, lg0 = (tid & 3) << 3;
    const int lr1 = (tid + 256) >> 2, lg1 = ((tid + 256) & 3) << 3;
    int mm0 = m0 + lr0; if (mm0 >= M) mm0 = M - 1;
    int mm1 = m0 + lr1; if (mm1 >= M) mm1 = M - 1;

    auto issue_chunk = [&](int c) {
        const uint32_t bb = sb + (uint32_t)(c % 3) * BUFSTR;
        const int k0 = c << 5;
#pragma unroll
        for (int it = 0; it < 2; ++it) {
            int r = it ? lr1 : lr0, g = it ? lg1 : lg0;
            int mm = it ? mm1 : mm0;
            int kg = k0 + g;
            uint32_t off = (uint32_t)(r * PITCH + g * 2);
            cp16(bb + off, AhG + (size_t)mm * K + kg);
            cp16(bb + ARR + off, AlG + (size_t)mm * K + kg);
        }
#pragma unroll
        for (int it = 0; it < 2; ++it) {
            int r = it ? lr1 : lr0, g = it ? lg1 : lg0;
            size_t so = (size_t)r * K + k0 + g;
            uint32_t off = (uint32_t)(r * PITCH + g * 2);
            cp16(bb + 2 * ARR + off, BT + so);
        }
        CP_COMMIT();
    };

    float acc[2][8][4];
#pragma unroll
    for (int i = 0; i < 2; i++)
#pragma unroll
        for (int j = 0; j < 8; j++)
#pragma unroll
            for (int q = 0; q < 4; q++) acc[i][j][q] = 0.f;

    const int nCh = K >> 5;
    issue_chunk(0);
    if (nCh > 1) issue_chunk(1);
    for (int c = 0; c < nCh; ++c) {
        if (c + 1 < nCh) CP_WAIT1();
        else CP_WAIT0();
        __syncthreads();
        const uint32_t bb = sb + (uint32_t)(c % 3) * BUFSTR;
#pragma unroll
        for (int ks = 0; ks < 2; ++ks) {
            const uint32_t kb = (uint32_t)((ks * 16 + coloff) * 2);
            uint32_t ah[2][4], al[2][4];
#pragma unroll
            for (int ma = 0; ma < 2; ++ma) {
                uint32_t ro = (uint32_t)((mrow0 + ma * 16 + rowoff) * PITCH) + kb;
                ldsm4(ah[ma], bb + ro);
                ldsm4(al[ma], bb + ARR + ro);
            }
            uint32_t bh[8][2];
#pragma unroll
            for (int ng = 0; ng < 4; ++ng) {
                uint32_t ro = (uint32_t)((ncol0 + ng * 16 + rowoff) * PITCH) + kb;
                uint32_t t[4];
                ldsm4(t, bb + 2 * ARR + ro);
                bh[2 * ng][0] = t[0]; bh[2 * ng][1] = t[2];
                bh[2 * ng + 1][0] = t[1]; bh[2 * ng + 1][1] = t[3];
            }
#pragma unroll
            for (int ma = 0; ma < 2; ++ma)
#pragma unroll
                for (int na = 0; na < 8; ++na) mma16816(acc[ma][na], ah[ma], bh[na]);
#pragma unroll
            for (int ma = 0; ma < 2; ++ma)
#pragma unroll
                for (int na = 0; na < 8; ++na) mma16816(acc[ma][na], al[ma], bh[na]);
        }
        if (c + 2 < nCh) issue_chunk(c + 2);
    }

    const int qr = lane >> 2, qc = (lane & 3) * 2;
    float (*pS)[2] = (float(*)[2])(sm + SM_PART);
    float (*pQ)[2] = (float(*)[2])(sm + SM_PART + 1024);
    const int nh = wid >> 2;
    float s[2][2] = {{0.f, 0.f}, {0.f, 0.f}};
    float q[2][2] = {{0.f, 0.f}, {0.f, 0.f}};
#pragma unroll
    for (int ma = 0; ma < 2; ++ma) {
        int mA = m0 + mrow0 + ma * 16 + qr;
        int mB = mA + 8;
#pragma unroll
        for (int na = 0; na < 8; ++na) {
            int n = ncol0 + na * 8 + qc;
            float pA0 = acc[ma][na][0] + bias[n];
            float pA1 = acc[ma][na][1] + bias[n + 1];
            float pB0 = acc[ma][na][2] + bias[n];
            float pB1 = acc[ma][na][3] + bias[n + 1];
            float oA0 = 0.f, oA1 = 0.f, oB0 = 0.f, oB1 = 0.f;
            if (mA < M) {
                if (rawOut) *(float2*)(rawOut + (size_t)mA * 128 + n) = make_float2(pA0, pA1);
                oA0 = pA0 + resid[(size_t)mA * 128 + n];
                oA1 = pA1 + resid[(size_t)mA * 128 + n + 1];
            }
            if (mB < M) {
                if (rawOut) *(float2*)(rawOut + (size_t)mB * 128 + n) = make_float2(pB0, pB1);
                oB0 = pB0 + resid[(size_t)mB * 128 + n];
                oB1 = pB1 + resid[(size_t)mB * 128 + n + 1];
            }
            acc[ma][na][0] = oA0; acc[ma][na][1] = oA1;
            acc[ma][na][2] = oB0; acc[ma][na][3] = oB1;
            s[ma][0] += oA0 + oA1; q[ma][0] += oA0 * oA0 + oA1 * oA1;
            s[ma][1] += oB0 + oB1; q[ma][1] += oB0 * oB0 + oB1 * oB1;
        }
    }
#pragma unroll
    for (int ma = 0; ma < 2; ++ma)
#pragma unroll
        for (int g2 = 0; g2 < 2; ++g2) {
            s[ma][g2] += __shfl_xor_sync(0xffffffffu, s[ma][g2], 1);
            s[ma][g2] += __shfl_xor_sync(0xffffffffu, s[ma][g2], 2);
            q[ma][g2] += __shfl_xor_sync(0xffffffffu, q[ma][g2], 1);
            q[ma][g2] += __shfl_xor_sync(0xffffffffu, q[ma][g2], 2);
        }
    __syncthreads();
    if ((lane & 3) == 0) {
#pragma unroll
        for (int ma = 0; ma < 2; ++ma) {
            int r = mrow0 + ma * 16 + qr;
            pS[r][nh] = s[ma][0]; pQ[r][nh] = q[ma][0];
            pS[r + 8][nh] = s[ma][1]; pQ[r + 8][nh] = q[ma][1];
        }
    }
    __syncthreads();
    float mean_[2][2], rstd_[2][2];
#pragma unroll
    for (int ma = 0; ma < 2; ++ma)
#pragma unroll
        for (int g2 = 0; g2 < 2; ++g2) {
            int r = mrow0 + ma * 16 + g2 * 8 + qr;
            float mu = (pS[r][0] + pS[r][1]) * (1.0f / 128.0f);
            float var = (pQ[r][0] + pQ[r][1]) * (1.0f / 128.0f) - mu * mu;
            mean_[ma][g2] = mu;
            rstd_[ma][g2] = rsqrtf(var + 1e-5f);
        }
#pragma unroll
    for (int ma = 0; ma < 2; ++ma) {
        int mA = m0 + mrow0 + ma * 16 + qr;
        int mB = mA + 8;
#pragma unroll
        for (int na = 0; na < 8; ++na) {
            int n = ncol0 + na * 8 + qc;
            float g0 = lnG[n], g1 = lnG[n + 1], b0 = lnB[n], b1 = lnB[n + 1];
            if (mA < M) {
                float yA0 = (acc[ma][na][0] - mean_[ma][0]) * rstd_[ma][0] * g0 + b0;
                float yA1 = (acc[ma][na][1] - mean_[ma][0]) * rstd_[ma][0] * g1 + b1;
                *(float2*)(Cout + (size_t)mA * 128 + n) = make_float2(yA0, yA1);
                if (outSplit) {
                    __half h0, l0, h1, l1;
                    split2h(yA0, h0, l0); split2h(yA1, h1, l1);
                    *(uint32_t*)(CoH + (size_t)mA * 128 + n) = packh(h0, h1);
                    *(uint32_t*)(CoL + (size_t)mA * 128 + n) = packh(l0, l1);
                }
            }
            if (mB < M) {
                float yB0 = (acc[ma][na][2] - mean_[ma][1]) * rstd_[ma][1] * g0 + b0;
                float yB1 = (acc[ma][na][3] - mean_[ma][1]) * rstd_[ma][1] * g1 + b1;
                *(float2*)(Cout + (size_t)mB * 128 + n) = make_float2(yB0, yB1);
                if (outSplit) {
                    __half h0, l0, h1, l1;
                    split2h(yB0, h0, l0); split2h(yB1, h1, l1);
                    *(uint32_t*)(CoH + (size_t)mB * 128 + n) = packh(h0, h1);
                    *(uint32_t*)(CoL + (size_t)mB * 128 + n) = packh(l0, l1);
                }
            }
        }
    }
}

// ---------------- weight transpose to fp16 ----------------
struct TEnt { const float* src; int dstOff; int K; int N; };
struct TTab { TEnt e[26]; };
__global__ void tsplit_k(TTab tab) {
    TEnt E = tab.e[blockIdx.y];
    int i = blockIdx.x * 256 + threadIdx.x;
    int total = E.K * E.N;
    if (i >= total) return;
    int k = i / E.N, n = i % E.N;
    g_wT[E.dstOff + (size_t)n * E.K + k] = __float2half_rn(E.src[i]);
}

// ---------------- setup ----------------
__global__ void embed_k(const int* __restrict__ seq, const float* __restrict__ emb) {
    int i = blockIdx.x * 256 + threadIdx.x;
    if (i < Nn * 128) {
        int nidx = i >> 7, d = i & 127;
        float x = emb[seq[nidx] * 128 + d];
        g_nodes[i] = x;
        __half h, l;
        split2h(x, h, l);
        g_nodesH[i] = h; g_nodesL[i] = l;
    }
}
__global__ void rbf_k(const float* __restrict__ dist, const float* __restrict__ W,
                      const float* __restrict__ b) {
    __shared__ float r[16];
    int e = blockIdx.x;
    int t = threadIdx.x;
    if (t < 16) {
        float mu = 2.0f + (20.0f / 15.0f) * (float)t;
        float x = (dist[e] - mu) * (1.0f / 1.25f);
        r[t] = expf(-x * x) + 1e-8f;
    }
    __syncthreads();
    float s = b[t];
#pragma unroll
    for (int j = 0; j < 16; j++) s += r[j] * W[j * 128 + t];
    long long i = (long long)e * 128 + t;
    g_eattr[i] = s;
    __half h, l;
    split2h(s, h, l);
    g_eatH[i] = h; g_eatL[i] = l;
}

// ---------------- CSR ----------------
__global__ void zero_cnt_k() {
    int i = blockIdx.x * 256 + threadIdx.x;
    if (i < Nn) g_cnt[i] = 0;
}
__global__ void count_k(const int* __restrict__ snk) {
    int e = blockIdx.x * 256 + threadIdx.x;
    if (e < Ee) atomicAdd(&g_cnt[snk[e]], 1);
}
__global__ void __launch_bounds__(1024) scan_k() {
    __shared__ int s[1024];
    int t = threadIdx.x;
    const int CH = (Nn + 1023) / 1024;
    int st = t * CH;
    int en = st + CH; if (en > Nn) en = Nn; if (st > Nn) st = Nn;
    int loc = 0;
    for (int i = st; i < en; i++) loc += g_cnt[i];
    s[t] = loc;
    __syncthreads();
    for (int d = 1; d < 1024; d <<= 1) {
        int v = (t >= d) ? s[t - d] : 0;
        __syncthreads();
        s[t] += v;
        __syncthreads();
    }
    int run = (t == 0) ? 0 : s[t - 1];
    for (int i = st; i < en; i++) {
        g_off[i] = run; g_cur[i] = run; run += g_cnt[i];
    }
    if (t == 1023) g_off[Nn] = s[1023];
}
__global__ void place_k(const int* __restrict__ snk) {
    int e = blockIdx.x * 256 + threadIdx.x;
    if (e < Ee) {
        int p = atomicAdd(&g_cur[snk[e]], 1);
        g_csr[p] = e;
    }
}

// ---------------- per-node softmax + aggregation ----------------
__global__ void __launch_bounds__(128) agg_k() {
    __shared__ float red[4][128];
    int n = blockIdx.x, t = threadIdx.x;
    int beg = g_off[n], end = g_off[n + 1];
    float4* sc4 = (float4*)g_scores;

    float mx[4] = {-1e30f, -1e30f, -1e30f, -1e30f};
    for (int i = beg + t; i < end; i += 128) {
        float4 s = sc4[g_csr[i]];
        mx[0] = fmaxf(mx[0], s.x); mx[1] = fmaxf(mx[1], s.y);
        mx[2] = fmaxf(mx[2], s.z); mx[3] = fmaxf(mx[3], s.w);
    }
#pragma unroll
    for (int h = 0; h < 4; h++) red[h][t] = mx[h];
    __syncthreads();
    for (int s = 64; s > 0; s >>= 1) {
        if (t < s)
#pragma unroll
            for (int h = 0; h < 4; h++) red[h][t] = fmaxf(red[h][t], red[h][t + s]);
        __syncthreads();
    }
    float mxf[4];
#pragma unroll
    for (int h = 0; h < 4; h++) mxf[h] = red[h][0];
    __syncthreads();

    float sm[4] = {0.f, 0.f, 0.f, 0.f};
    for (int i = beg + t; i < end; i += 128) {
        float4 s = sc4[g_csr[i]];
        sm[0] += expf(s.x - mxf[0]) + 1e-12f;
        sm[1] += expf(s.y - mxf[1]) + 1e-12f;
        sm[2] += expf(s.z - mxf[2]) + 1e-12f;
        sm[3] += expf(s.w - mxf[3]) + 1e-12f;
    }
#pragma unroll
    for (int h = 0; h < 4; h++) red[h][t] = sm[h];
    __syncthreads();
    for (int s = 64; s > 0; s >>= 1) {
        if (t < s)
#pragma unroll
            for (int h = 0; h < 4; h++) red[h][t] += red[h][t + s];
        __syncthreads();
    }
    float nrm[4];
#pragma unroll
    for (int h = 0; h < 4; h++) nrm[h] = red[h][0];

    // pass 2b: materialize att in place (each edge read only by its own sink block)
    for (int i = beg + t; i < end; i += 128) {
        int e = g_csr[i];
        float4 s = sc4[e];
        s.x = expf(s.x - mxf[0]) / nrm[0];
        s.y = expf(s.y - mxf[1]) / nrm[1];
        s.z = expf(s.z - mxf[2]) / nrm[2];
        s.w = expf(s.w - mxf[3]) / nrm[3];
        sc4[e] = s;
    }
    __syncthreads();

    float acc[4] = {0.f, 0.f, 0.f, 0.f};
    for (int i = beg; i < end; i++) {
        int e = g_csr[i];
        float4 a = sc4[e];
        float v = g_nupd[(long long)e * 128 + t];
        acc[0] += a.x * v; acc[1] += a.y * v; acc[2] += a.z * v; acc[3] += a.w * v;
    }
    long long base = (long long)n * 512;
#pragma unroll
    for (int h = 0; h < 4; h++) {
        __half hh, ll;
        split2h(acc[h], hh, ll);
        g_aggH[base + h * 128 + t] = hh;
        g_aggL[base + h * 128 + t] = ll;
    }
}

// ---------------- host ----------------
extern "C" void kernel_launch(void* const* d_in, const int* in_sizes, int n_in,
                              void* d_out, int out_size) {
    const int* seq = (const int*)d_in[0];
    const int* eidx = (const int*)d_in[1];
    const int* srcI = eidx;
    const int* snkI = eidx + Ee;
    const float* dist = (const float*)d_in[2];
    const float* seq_embed = (const float*)d_in[3];
    const float* edge_lin_W = (const float*)d_in[4];
    const float* edge_lin_b = (const float*)d_in[5];
    const float* aW_W = (const float*)d_in[6];
    const float* aW_b = (const float*)d_in[7];
    const float* aA_W = (const float*)d_in[8];
    const float* aA_b = (const float*)d_in[9];
    const float* nmlp_W1 = (const float*)d_in[10];
    const float* nmlp_b1 = (const float*)d_in[11];
    const float* nmlp_W2 = (const float*)d_in[12];
    const float* nmlp_b2 = (const float*)d_in[13];
    const float* nmlp_W3 = (const float*)d_in[14];
    const float* nmlp_b3 = (const float*)d_in[15];
    const float* dmlp_W1 = (const float*)d_in[16];
    const float* dmlp_b1 = (const float*)d_in[17];
    const float* dmlp_W2 = (const float*)d_in[18];
    const float* dmlp_b2 = (const float*)d_in[19];
    const float* emlp_W1 = (const float*)d_in[20];
    const float* emlp_b1 = (const float*)d_in[21];
    const float* emlp_W2 = (const float*)d_in[22];
    const float* emlp_b2 = (const float*)d_in[23];
    const float* emlp_W3 = (const float*)d_in[24];
    const float* emlp_b3 = (const float*)d_in[25];
    const float* aggr_W = (const float*)d_in[26];
    const float* aggr_b = (const float*)d_in[27];
    const float* n1_g = (const float*)d_in[28];
    const float* n1_b = (const float*)d_in[29];
    const float* e_g = (const float*)d_in[30];
    const float* e_b = (const float*)d_in[31];

    float *p_nodes, *p_eattr, *p_nupd, *p_scores, *p_upd;
    __half *pW, *pNh, *pNl, *pEh, *pEl, *pB1h, *pB1l, *pB2h, *pB2l, *pAgh, *pAgl;
    cudaGetSymbolAddress((void**)&p_nodes, g_nodes);
    cudaGetSymbolAddress((void**)&p_eattr, g_eattr);
    cudaGetSymbolAddress((void**)&p_nupd, g_nupd);
    cudaGetSymbolAddress((void**)&p_scores, g_scores);
    cudaGetSymbolAddress((void**)&p_upd, g_upd);
    cudaGetSymbolAddress((void**)&pW, g_wT);
    cudaGetSymbolAddress((void**)&pNh, g_nodesH);
    cudaGetSymbolAddress((void**)&pNl, g_nodesL);
    cudaGetSymbolAddress((void**)&pEh, g_eatH);
    cudaGetSymbolAddress((void**)&pEl, g_eatL);
    cudaGetSymbolAddress((void**)&pB1h, g_b1H);
    cudaGetSymbolAddress((void**)&pB1l, g_b1L);
    cudaGetSymbolAddress((void**)&pB2h, g_b2H);
    cudaGetSymbolAddress((void**)&pB2l, g_b2L);
    cudaGetSymbolAddress((void**)&pAgh, g_aggH);
    cudaGetSymbolAddress((void**)&pAgl, g_aggL);

    cudaFuncSetAttribute(gemm_tc, cudaFuncAttributeMaxDynamicSharedMemorySize, SM_TOTAL);
    cudaFuncSetAttribute(gemm_ln, cudaFuncAttributeMaxDynamicSharedMemorySize, SM_TOTAL_LN);

    TTab tab;
    {
        int idx = 0;
        for (int l = 0; l < 2; l++) {
            int lb = l * WT_LAYER;
            for (int h = 0; h < 4; h++)
                tab.e[idx++] = { aW_W + (size_t)(l * 4 + h) * 384 * 128, lb + h * 49152, 384, 128 };
            tab.e[idx++] = { nmlp_W1 + (size_t)l * 384 * 128, lb + 196608, 384, 128 };
            tab.e[idx++] = { nmlp_W2 + (size_t)l * 128 * 128, lb + 245760, 128, 128 };
            tab.e[idx++] = { nmlp_W3 + (size_t)l * 128 * 128, lb + 262144, 128, 128 };
            tab.e[idx++] = { aggr_W + (size_t)l * 512 * 128, lb + 278528, 512, 128 };
            tab.e[idx++] = { dmlp_W1 + (size_t)l * 128 * 512, lb + 344064, 128, 512 };
            tab.e[idx++] = { dmlp_W2 + (size_t)l * 512 * 128, lb + 409600, 512, 128 };
            tab.e[idx++] = { emlp_W1 + (size_t)l * 384 * 128, lb + 475136, 384, 128 };
            tab.e[idx++] = { emlp_W2 + (size_t)l * 128 * 128, lb + 524288, 128, 128 };
            tab.e[idx++] = { emlp_W3 + (size_t)l * 128 * 128, lb + 540672, 128, 128 };
        }
    }

    auto gemm = [&](int M, int K, int nTile, int zDim,
                    const __half* Ah, const __half* Al, long long wOff,
                    const float* bias, float* Cp, __half* CoH, __half* CoL,
                    int ldc, int act, int feat, int osplit,
                    const float* aAv, const float* aAb, const float* bias4) {
        dim3 g(nTile, (M + 127) / 128, zDim);
        gemm_tc<<<g, 256, SM_TOTAL>>>(M, K, Ah, Al, pW + wOff, bias, Cp, CoH, CoL, ldc,
                                      act, feat, osplit, pNh, pNl, pEh, pEl, srcI, snkI,
                                      aAv, aAb, bias4);
    };
    auto gemmLN = [&](int M, int K, const __half* Ah, const __half* Al, long long wOff,
                      const float* bias, float* Cp, __half* CoH, __half* CoL, int osplit,
                      const float* resid, const float* lnG, const float* lnB, float* rawOut) {
        dim3 g(1, (M + 127) / 128, 1);
        gemm_ln<<<g, 256, SM_TOTAL_LN>>>(M, K, Ah, Al, pW + wOff, bias, Cp, CoH, CoL, osplit,
                                         resid, lnG, lnB, rawOut);
    };

    tsplit_k<<<dim3(256, 26), 256>>>(tab);
    embed_k<<<(Nn * 128 + 255) / 256, 256>>>(seq, seq_embed);
    rbf_k<<<Ee, 128>>>(dist, edge_lin_W, edge_lin_b);
    zero_cnt_k<<<(Nn + 255) / 256, 256>>>();
    count_k<<<(Ee + 255) / 256, 256>>>(snkI);
    scan_k<<<1, 1024>>>();
    place_k<<<(Ee + 255) / 256, 256>>>(snkI);

    float* outNodes = (float*)d_out;
    float* outEattr = (float*)d_out + (long long)Nn * 128;

    for (int l = 0; l < 2; l++) {
        long long lb = (long long)l * WT_LAYER;
        // fused: attention scores (z=0..3) + nmlp1 (z=4; weights contiguous after heads)
        gemm(Ee, Cc, 1, 5, nullptr, nullptr, lb + 0, aW_b + l * 512,
             p_scores, pB1h, pB1l, 128, 2, 1, 0, aA_W + l * 512, aA_b + l * 4,
             nmlp_b1 + l * 128);
        gemm(Ee, 128, 1, 1, pB1h, pB1l, lb + 245760, nmlp_b2 + l * 128,
             nullptr, pB2h, pB2l, 128, 1, 0, 1, nullptr, nullptr, nullptr);
        gemm(Ee, 128, 1, 1, pB2h, pB2l, lb + 262144, nmlp_b3 + l * 128,
             p_nupd, nullptr, nullptr, 128, 0, 0, 0, nullptr, nullptr, nullptr);
        agg_k<<<Nn, 128>>>();
        gemmLN(Nn, 512, pAgh, pAgl, lb + 278528, aggr_b + l * 128,
               p_nodes, pNh, pNl, 1, p_nodes, n1_g + l * 128, n1_b + l * 128, p_upd);
        gemm(Nn, 128, 4, 1, pNh, pNl, lb + 344064, dmlp_b1 + l * 512,
             nullptr, pB1h, pB1l, 512, 1, 0, 1, nullptr, nullptr, nullptr);
        gemmLN(Nn, 512, pB1h, pB1l, lb + 409600, dmlp_b2 + l * 128,
               l == 1 ? outNodes : p_nodes, pNh, pNl, 1,
               p_upd, n1_g + l * 128, n1_b + l * 128, nullptr);
        gemm(Ee, Cc, 1, 1, nullptr, nullptr, lb + 475136, emlp_b1 + l * 128,
             nullptr, pB1h, pB1l, 128, 1, 1, 1, nullptr, nullptr, nullptr);
        gemm(Ee, 128, 1, 1, pB1h, pB1l, lb + 524288, emlp_b2 + l * 128,
             nullptr, pB2h, pB2l, 128, 1, 0, 1, nullptr, nullptr, nullptr);
        gemmLN(Ee, 128, pB2h, pB2l, lb + 540672, emlp_b3 + l * 128,
               l == 1 ? outEattr : p_eattr, pEh, pEl, l == 0 ? 1 : 0,
               p_eattr, e_g + l * 128, e_b + l * 128, nullptr);
    }
}